// round 1
// baseline (speedup 1.0000x reference)
#include <cuda_runtime.h>
#include <cuda_bf16.h>
#include <math.h>

// Problem constants
#define BATCH   2
#define SEQ     2048
#define DMODEL  2048
#define NHEADS  16
#define DHEAD   128
#define MROWS   (BATCH*SEQ)          // 4096
#define QKVDIM  (3*DMODEL)           // 6144

// Scratch (allocation-free rule: __device__ globals)
__device__ float g_qkv[(size_t)MROWS * QKVDIM];   // [b*T+t][6144]  (q|k|v)
__device__ float g_att[(size_t)MROWS * DMODEL];   // attention output pre-WO

// ---------------------------------------------------------------------------
// GEMM (NT): C[M,N] = A[M,K] * B[N,K]^T   (both row-major, K contiguous)
// 128x128 block, BK=16, 256 threads, 8x8 microtile (split 4+4).
// ---------------------------------------------------------------------------
#define GBM 128
#define GBN 128
#define GBK 16

__global__ __launch_bounds__(256) void gemm_nt_kernel(
    const float* __restrict__ A, const float* __restrict__ B,
    float* __restrict__ C, int M, int N, int K)
{
    __shared__ float As[GBK][GBM + 4];   // stride 132: 16B-aligned vec reads
    __shared__ float Bs[GBK][GBN + 4];

    const int tid = threadIdx.x;
    const int tx  = tid & 15;
    const int ty  = tid >> 4;
    const int bm  = blockIdx.y * GBM;
    const int bn  = blockIdx.x * GBN;

    float acc[8][8];
#pragma unroll
    for (int i = 0; i < 8; i++)
#pragma unroll
        for (int j = 0; j < 8; j++) acc[i][j] = 0.f;

    for (int k0 = 0; k0 < K; k0 += GBK) {
        // Load tiles: 128 rows x 16 k, float4 along k; transpose into smem.
#pragma unroll
        for (int it = 0; it < 2; it++) {
            int idx = tid + it * 256;          // 0..511
            int r   = idx >> 2;                // 0..127
            int k4  = idx & 3;                 // 0..3
            float4 av = *reinterpret_cast<const float4*>(
                &A[(size_t)(bm + r) * K + k0 + k4 * 4]);
            As[k4*4+0][r] = av.x; As[k4*4+1][r] = av.y;
            As[k4*4+2][r] = av.z; As[k4*4+3][r] = av.w;
            float4 bv = *reinterpret_cast<const float4*>(
                &B[(size_t)(bn + r) * K + k0 + k4 * 4]);
            Bs[k4*4+0][r] = bv.x; Bs[k4*4+1][r] = bv.y;
            Bs[k4*4+2][r] = bv.z; Bs[k4*4+3][r] = bv.w;
        }
        __syncthreads();

#pragma unroll
        for (int kk = 0; kk < GBK; ++kk) {
            float a[8], b[8];
            *reinterpret_cast<float4*>(&a[0]) =
                *reinterpret_cast<const float4*>(&As[kk][ty * 4]);
            *reinterpret_cast<float4*>(&a[4]) =
                *reinterpret_cast<const float4*>(&As[kk][64 + ty * 4]);
            *reinterpret_cast<float4*>(&b[0]) =
                *reinterpret_cast<const float4*>(&Bs[kk][tx * 4]);
            *reinterpret_cast<float4*>(&b[4]) =
                *reinterpret_cast<const float4*>(&Bs[kk][64 + tx * 4]);
#pragma unroll
            for (int i = 0; i < 8; i++)
#pragma unroll
                for (int j = 0; j < 8; j++)
                    acc[i][j] += a[i] * b[j];
        }
        __syncthreads();
    }

    // Write back (two float4 per row-slot)
#pragma unroll
    for (int i = 0; i < 8; i++) {
        int rm = bm + ((i < 4) ? (ty * 4 + i) : (64 + ty * 4 + (i - 4)));
        float4 v0, v1;
        v0.x = acc[i][0]; v0.y = acc[i][1]; v0.z = acc[i][2]; v0.w = acc[i][3];
        v1.x = acc[i][4]; v1.y = acc[i][5]; v1.z = acc[i][6]; v1.w = acc[i][7];
        *reinterpret_cast<float4*>(&C[(size_t)rm * N + bn + tx * 4])      = v0;
        *reinterpret_cast<float4*>(&C[(size_t)rm * N + bn + 64 + tx * 4]) = v1;
    }
}

// ---------------------------------------------------------------------------
// RoPE applied in-place to q and k slices of g_qkv.
// One thread per (b,t,h,pair). fp64 phase for accuracy at large t.
// ---------------------------------------------------------------------------
__global__ __launch_bounds__(256) void rope_kernel(float* __restrict__ qkv)
{
    int idx = blockIdx.x * 256 + threadIdx.x;    // < B*T*H*64 = 4194304
    int i = idx & 63;
    int h = (idx >> 6) & (NHEADS - 1);
    int t = (idx >> 10) & (SEQ - 1);
    int b = idx >> 21;

    double freq = exp(-9.210340371976184 * (double)(2 * i) / 128.0); // 10000^(-2i/128)
    double ang  = (double)t * freq;
    double sd, cd;
    sincos(ang, &sd, &cd);
    float s = (float)sd, c = (float)cd;

    size_t base = ((size_t)(b * SEQ + t)) * QKVDIM + h * DHEAD + 2 * i;
    float2 q = *reinterpret_cast<float2*>(&qkv[base]);
    float2 k = *reinterpret_cast<float2*>(&qkv[base + DMODEL]);
    float2 qo, ko;
    qo.x = q.x * c - q.y * s;  qo.y = q.y * c + q.x * s;
    ko.x = k.x * c - k.y * s;  ko.y = k.y * c + k.x * s;
    *reinterpret_cast<float2*>(&qkv[base])          = qo;
    *reinterpret_cast<float2*>(&qkv[base + DMODEL]) = ko;
}

// ---------------------------------------------------------------------------
// Flash attention, causal. 64-query x 64-key tiles, Dh=128, fp32.
// 256 threads: S via 16x16 grid of 4x4 microtiles; PV with 4 threads/row,
// each holding 32 of 128 d-values in registers.
// ---------------------------------------------------------------------------
#define TQ 64
#define TK 64

struct AttnSmem {
    float Qt[DHEAD][65];   // transposed Q (scaled), pad 65
    float Kt[DHEAD][65];   // transposed K
    float V [TK][132];     // row-major V, pad 132 (16B-aligned rows)
    float S [TQ][65];
    float m[TQ], l[TQ], f[TQ];
};

__global__ __launch_bounds__(256) void attn_kernel(
    const float* __restrict__ qkv, float* __restrict__ out)
{
    extern __shared__ char smem_raw[];
    AttnSmem& sm = *reinterpret_cast<AttnSmem*>(smem_raw);

    const int qt = gridDim.x - 1 - blockIdx.x;   // heavy tiles launch first
    const int h  = blockIdx.y;
    const int b  = blockIdx.z;
    const int tid = threadIdx.x;
    const int q0 = qt * TQ;
    const float scale = 0.08838834764831845f;    // 1/sqrt(128)

    const float* qbase = qkv + (size_t)b * SEQ * QKVDIM + h * DHEAD;

    // Load Q tile (transposed, pre-scaled)
    for (int i = tid; i < TQ * 32; i += 256) {
        int r  = i >> 5;
        int d4 = i & 31;
        float4 v = *reinterpret_cast<const float4*>(
            qbase + (size_t)(q0 + r) * QKVDIM + d4 * 4);
        sm.Qt[d4*4+0][r] = v.x * scale;
        sm.Qt[d4*4+1][r] = v.y * scale;
        sm.Qt[d4*4+2][r] = v.z * scale;
        sm.Qt[d4*4+3][r] = v.w * scale;
    }
    if (tid < TQ) { sm.m[tid] = -1e30f; sm.l[tid] = 0.f; }

    float O[32];
#pragma unroll
    for (int j = 0; j < 32; j++) O[j] = 0.f;

    const int r_own = tid >> 2;     // PV row ownership
    const int c4    = tid & 3;
    const int tx    = tid & 15;
    const int ty    = tid >> 4;

    for (int kt = 0; kt <= qt; ++kt) {
        const int k0 = kt * TK;
        __syncthreads();   // prev PV done before K/V overwrite; Q ready (iter 0)

        const float* kbase = qkv + ((size_t)(b * SEQ) + k0) * QKVDIM + DMODEL  + h * DHEAD;
        const float* vbase = kbase + DMODEL;
        for (int i = tid; i < TK * 32; i += 256) {
            int r  = i >> 5;
            int d4 = i & 31;
            float4 kv = *reinterpret_cast<const float4*>(kbase + (size_t)r * QKVDIM + d4 * 4);
            sm.Kt[d4*4+0][r] = kv.x; sm.Kt[d4*4+1][r] = kv.y;
            sm.Kt[d4*4+2][r] = kv.z; sm.Kt[d4*4+3][r] = kv.w;
            float4 vv = *reinterpret_cast<const float4*>(vbase + (size_t)r * QKVDIM + d4 * 4);
            *reinterpret_cast<float4*>(&sm.V[r][d4 * 4]) = vv;
        }
        __syncthreads();

        // S = (Q*scale) @ K^T, 4x4 per thread
        float acc[4][4];
#pragma unroll
        for (int i = 0; i < 4; i++)
#pragma unroll
            for (int j = 0; j < 4; j++) acc[i][j] = 0.f;

#pragma unroll 16
        for (int kk = 0; kk < DHEAD; ++kk) {
            float a0 = sm.Qt[kk][ty*4+0], a1 = sm.Qt[kk][ty*4+1];
            float a2 = sm.Qt[kk][ty*4+2], a3 = sm.Qt[kk][ty*4+3];
            float b0 = sm.Kt[kk][tx*4+0], b1 = sm.Kt[kk][tx*4+1];
            float b2 = sm.Kt[kk][tx*4+2], b3 = sm.Kt[kk][tx*4+3];
            acc[0][0] += a0*b0; acc[0][1] += a0*b1; acc[0][2] += a0*b2; acc[0][3] += a0*b3;
            acc[1][0] += a1*b0; acc[1][1] += a1*b1; acc[1][2] += a1*b2; acc[1][3] += a1*b3;
            acc[2][0] += a2*b0; acc[2][1] += a2*b1; acc[2][2] += a2*b2; acc[2][3] += a2*b3;
            acc[3][0] += a3*b0; acc[3][1] += a3*b1; acc[3][2] += a3*b2; acc[3][3] += a3*b3;
        }
#pragma unroll
        for (int i = 0; i < 4; i++) {
            int r = ty * 4 + i;
#pragma unroll
            for (int j = 0; j < 4; j++) {
                int c = tx * 4 + j;
                float v = acc[i][j];
                if (k0 + c > q0 + r) v = -1e30f;   // causal mask (diag tile only)
                sm.S[r][c] = v;
            }
        }
        __syncthreads();

        // Online softmax per row (threads 0..63)
        if (tid < TQ) {
            int r = tid;
            float mo = sm.m[r];
            float mx = mo;
#pragma unroll 8
            for (int c = 0; c < TK; c++) mx = fmaxf(mx, sm.S[r][c]);
            float fac = __expf(mo - mx);
            float sum = 0.f;
#pragma unroll 8
            for (int c = 0; c < TK; c++) {
                float p = __expf(sm.S[r][c] - mx);
                sm.S[r][c] = p;
                sum += p;
            }
            sm.m[r] = mx;
            sm.l[r] = sm.l[r] * fac + sum;
            sm.f[r] = fac;
        }
        __syncthreads();

        // Rescale + PV accumulate
        float fac = sm.f[r_own];
#pragma unroll
        for (int j = 0; j < 32; j++) O[j] *= fac;

#pragma unroll 4
        for (int k = 0; k < TK; k++) {
            float p = sm.S[r_own][k];
#pragma unroll
            for (int jj = 0; jj < 8; jj++) {
                float4 vv = *reinterpret_cast<const float4*>(&sm.V[k][jj * 16 + c4 * 4]);
                O[jj*4+0] += p * vv.x;
                O[jj*4+1] += p * vv.y;
                O[jj*4+2] += p * vv.z;
                O[jj*4+3] += p * vv.w;
            }
        }
    }

    // Normalize & write: out[b, q0+r, h*128 + d], d = jj*16 + c4*4 + e
    float invl = 1.f / sm.l[r_own];
    float* obase = out + ((size_t)(b * SEQ) + q0 + r_own) * DMODEL + h * DHEAD;
#pragma unroll
    for (int jj = 0; jj < 8; jj++) {
        float4 v;
        v.x = O[jj*4+0] * invl; v.y = O[jj*4+1] * invl;
        v.z = O[jj*4+2] * invl; v.w = O[jj*4+3] * invl;
        *reinterpret_cast<float4*>(obase + jj * 16 + c4 * 4) = v;
    }
}

// ---------------------------------------------------------------------------
extern "C" void kernel_launch(void* const* d_in, const int* in_sizes, int n_in,
                              void* d_out, int out_size)
{
    const float* x    = (const float*)d_in[0];
    const float* Wqkv = (const float*)d_in[1];
    const float* WO   = (const float*)d_in[2];
    float* out = (float*)d_out;

    float *qkv, *att;
    cudaGetSymbolAddress((void**)&qkv, g_qkv);
    cudaGetSymbolAddress((void**)&att, g_att);

    // 1) qkv = x @ Wqkv^T    [4096,6144]
    {
        dim3 grid(QKVDIM / GBN, MROWS / GBM);
        gemm_nt_kernel<<<grid, 256>>>(x, Wqkv, qkv, MROWS, QKVDIM, DMODEL);
    }

    // 2) RoPE on q,k in place
    {
        int total = BATCH * SEQ * NHEADS * (DHEAD / 2);  // 4194304
        rope_kernel<<<total / 256, 256>>>(qkv);
    }

    // 3) causal flash attention -> g_att
    {
        int smem = (int)sizeof(AttnSmem);
        cudaFuncSetAttribute(attn_kernel,
                             cudaFuncAttributeMaxDynamicSharedMemorySize, smem);
        dim3 grid(SEQ / TQ, NHEADS, BATCH);
        attn_kernel<<<grid, 256, smem>>>(qkv, att);
    }

    // 4) out = att @ WO^T     [4096,2048]
    {
        dim3 grid(DMODEL / GBN, MROWS / GBM);
        gemm_nt_kernel<<<grid, 256>>>(att, WO, out, MROWS, DMODEL, DMODEL);
    }
}

// round 3
// speedup vs baseline: 1.4510x; 1.4510x over previous
#include <cuda_runtime.h>
#include <cuda_bf16.h>
#include <math.h>
#include <stdint.h>

// Problem constants
#define BATCH   2
#define SEQ     2048
#define DMODEL  2048
#define NHEADS  16
#define DHEAD   128
#define MROWS   (BATCH*SEQ)          // 4096
#define QKVDIM  (3*DMODEL)           // 6144
#define KDIM    2048

// Scratch (__device__ globals; allocation-free rule)
__device__ float g_qkv[(size_t)MROWS * QKVDIM];
__device__ float g_att[(size_t)MROWS * DMODEL];
__device__ __nv_bfloat16 g_xh[(size_t)MROWS * KDIM],   g_xl[(size_t)MROWS * KDIM];
__device__ __nv_bfloat16 g_wqh[(size_t)QKVDIM * KDIM], g_wql[(size_t)QKVDIM * KDIM];
__device__ __nv_bfloat16 g_ah[(size_t)MROWS * KDIM],   g_al[(size_t)MROWS * KDIM];
__device__ __nv_bfloat16 g_wh[(size_t)DMODEL * KDIM],  g_wl[(size_t)DMODEL * KDIM];

// ---------------------------------------------------------------------------
// PTX helpers (no tcgen05 — plain sm_103-legal instructions only)
// ---------------------------------------------------------------------------
static __device__ __forceinline__ uint32_t smem_u32(const void* p) {
    uint32_t a;
    asm("{ .reg .u64 t; cvta.to.shared.u64 t, %1; cvt.u32.u64 %0, t; }" : "=r"(a) : "l"(p));
    return a;
}
static __device__ __forceinline__ void cpasync16(uint32_t dst, const void* src) {
    asm volatile("cp.async.cg.shared.global [%0], [%1], 16;\n" :: "r"(dst), "l"(src));
}
#define CP_COMMIT() asm volatile("cp.async.commit_group;\n" ::: "memory")
#define CP_WAIT0()  asm volatile("cp.async.wait_group 0;\n" ::: "memory")
#define CP_WAIT1()  asm volatile("cp.async.wait_group 1;\n" ::: "memory")

static __device__ __forceinline__ void ldsm_x4(uint32_t& r0, uint32_t& r1,
                                               uint32_t& r2, uint32_t& r3, uint32_t a) {
    asm volatile("ldmatrix.sync.aligned.m8n8.x4.shared.b16 {%0,%1,%2,%3}, [%4];"
                 : "=r"(r0), "=r"(r1), "=r"(r2), "=r"(r3) : "r"(a));
}
static __device__ __forceinline__ void ldsm_x2(uint32_t& r0, uint32_t& r1, uint32_t a) {
    asm volatile("ldmatrix.sync.aligned.m8n8.x2.shared.b16 {%0,%1}, [%2];"
                 : "=r"(r0), "=r"(r1) : "r"(a));
}
static __device__ __forceinline__ void mma_bf16(float* c, const uint32_t* a, const uint32_t* b) {
    asm volatile(
        "mma.sync.aligned.m16n8k16.row.col.f32.bf16.bf16.f32 "
        "{%0,%1,%2,%3}, {%4,%5,%6,%7}, {%8,%9}, {%0,%1,%2,%3};"
        : "+f"(c[0]), "+f"(c[1]), "+f"(c[2]), "+f"(c[3])
        : "r"(a[0]), "r"(a[1]), "r"(a[2]), "r"(a[3]), "r"(b[0]), "r"(b[1]));
}

// ---------------------------------------------------------------------------
// fp32 -> bf16 hi/lo split
// ---------------------------------------------------------------------------
__global__ __launch_bounds__(256) void split_kernel(
    const float* __restrict__ s, __nv_bfloat16* __restrict__ hi,
    __nv_bfloat16* __restrict__ lo, int n)
{
    int i = blockIdx.x * 256 + threadIdx.x;
    if (i >= n) return;
    float v = s[i];
    __nv_bfloat16 h = __float2bfloat16(v);
    hi[i] = h;
    lo[i] = __float2bfloat16(v - __bfloat162float(h));
}

// ---------------------------------------------------------------------------
// mma.sync GEMM (NT): C[M,N] = A[M,K]*B[N,K]^T, bf16 hi/lo 3-term.
// BM=BN=128, BK=32, 256 threads = 8 warps (2m x 4n), warp tile 64x32.
// Double-buffered cp.async smem; padded rows (stride 40 elems = 80B).
// ---------------------------------------------------------------------------
#define BM 128
#define BN 128
#define BK 32
#define SROW 40                              // padded row stride (elems)
#define PART_BYTES (128 * SROW * 2)          // 10240 per matrix part
#define STG_BYTES  (4 * PART_BYTES)          // Ah|Al|Bh|Bl = 40960
#define AH_OFF 0
#define AL_OFF PART_BYTES
#define BH_OFF (2 * PART_BYTES)
#define BL_OFF (3 * PART_BYTES)
#define GSMEM (2 * STG_BYTES)                // 81920

static __device__ __forceinline__ void g_load_stage(
    uint32_t sb, int buf, int s, int bm, int bn, int tid,
    const __nv_bfloat16* __restrict__ Ah, const __nv_bfloat16* __restrict__ Al,
    const __nv_bfloat16* __restrict__ Bh, const __nv_bfloat16* __restrict__ Bl)
{
    uint32_t base = sb + buf * STG_BYTES;
    const int k0 = s * BK;
#pragma unroll
    for (int it = 0; it < 2; it++) {
        int idx = tid + it * 256;        // 0..511
        int r = idx >> 2, ch = idx & 3;  // row, 16B chunk
        uint32_t so = r * (SROW * 2) + ch * 16;
        size_t ga = (size_t)(bm + r) * KDIM + k0 + ch * 8;
        size_t gb = (size_t)(bn + r) * KDIM + k0 + ch * 8;
        cpasync16(base + AH_OFF + so, Ah + ga);
        cpasync16(base + AL_OFF + so, Al + ga);
        cpasync16(base + BH_OFF + so, Bh + gb);
        cpasync16(base + BL_OFF + so, Bl + gb);
    }
    CP_COMMIT();
}

__global__ __launch_bounds__(256, 2) void gemm_mma(
    const __nv_bfloat16* __restrict__ Ah, const __nv_bfloat16* __restrict__ Al,
    const __nv_bfloat16* __restrict__ Bh, const __nv_bfloat16* __restrict__ Bl,
    float* __restrict__ C, int ldc)
{
    extern __shared__ char smem[];
    uint32_t sb = smem_u32(smem);
    const int tid  = threadIdx.x;
    const int wid  = tid >> 5, lane = tid & 31;
    const int wm   = wid >> 2, wn = wid & 3;          // 2 x 4 warp grid
    const int bm   = blockIdx.y * BM, bn = blockIdx.x * BN;

    float acc[4][4][4];
#pragma unroll
    for (int i = 0; i < 4; i++)
#pragma unroll
        for (int j = 0; j < 4; j++)
#pragma unroll
            for (int e = 0; e < 4; e++) acc[i][j][e] = 0.f;

    // ldmatrix lane addresses (offsets within a part)
    const uint32_t aRow = wm * 64 + (lane & 15);          // + mt*16
    const uint32_t aCol = (lane >> 4) << 3;               // + kk
    const uint32_t bRow = wn * 32 + (lane & 7);           // + nt*8
    const uint32_t bCol = ((lane >> 3) & 1) << 3;         // + kk

    g_load_stage(sb, 0, 0, bm, bn, tid, Ah, Al, Bh, Bl);

    const int NS = KDIM / BK;   // 64
    for (int s = 0; s < NS; s++) {
        const int buf = s & 1;
        if (s + 1 < NS) {
            g_load_stage(sb, buf ^ 1, s + 1, bm, bn, tid, Ah, Al, Bh, Bl);
            CP_WAIT1();
        } else {
            CP_WAIT0();
        }
        __syncthreads();

        uint32_t base = sb + buf * STG_BYTES;
#pragma unroll
        for (int kk = 0; kk < BK; kk += 16) {
            uint32_t af[4][4], bf[4][2];
            // --- combo 1: Ah x Bh ---
#pragma unroll
            for (int mt = 0; mt < 4; mt++)
                ldsm_x4(af[mt][0], af[mt][1], af[mt][2], af[mt][3],
                        base + AH_OFF + (aRow + mt * 16) * (SROW * 2) + (aCol + kk) * 2);
#pragma unroll
            for (int nt = 0; nt < 4; nt++)
                ldsm_x2(bf[nt][0], bf[nt][1],
                        base + BH_OFF + (bRow + nt * 8) * (SROW * 2) + (bCol + kk) * 2);
#pragma unroll
            for (int mt = 0; mt < 4; mt++)
#pragma unroll
                for (int nt = 0; nt < 4; nt++) mma_bf16(acc[mt][nt], af[mt], bf[nt]);
            // --- combo 2: Al x Bh (reload A only) ---
#pragma unroll
            for (int mt = 0; mt < 4; mt++)
                ldsm_x4(af[mt][0], af[mt][1], af[mt][2], af[mt][3],
                        base + AL_OFF + (aRow + mt * 16) * (SROW * 2) + (aCol + kk) * 2);
#pragma unroll
            for (int mt = 0; mt < 4; mt++)
#pragma unroll
                for (int nt = 0; nt < 4; nt++) mma_bf16(acc[mt][nt], af[mt], bf[nt]);
            // --- combo 3: Ah x Bl (reload both) ---
#pragma unroll
            for (int nt = 0; nt < 4; nt++)
                ldsm_x2(bf[nt][0], bf[nt][1],
                        base + BL_OFF + (bRow + nt * 8) * (SROW * 2) + (bCol + kk) * 2);
#pragma unroll
            for (int mt = 0; mt < 4; mt++)
                ldsm_x4(af[mt][0], af[mt][1], af[mt][2], af[mt][3],
                        base + AH_OFF + (aRow + mt * 16) * (SROW * 2) + (aCol + kk) * 2);
#pragma unroll
            for (int mt = 0; mt < 4; mt++)
#pragma unroll
                for (int nt = 0; nt < 4; nt++) mma_bf16(acc[mt][nt], af[mt], bf[nt]);
        }
        __syncthreads();
    }

    // Epilogue: thread owns rows lane/4, lane/4+8; cols 2*(lane%4)+{0,1}
    const int r0 = bm + wm * 64 + (lane >> 2);
    const int c0 = bn + wn * 32 + 2 * (lane & 3);
#pragma unroll
    for (int mt = 0; mt < 4; mt++)
#pragma unroll
        for (int nt = 0; nt < 4; nt++) {
            float2 v0 = make_float2(acc[mt][nt][0], acc[mt][nt][1]);
            float2 v1 = make_float2(acc[mt][nt][2], acc[mt][nt][3]);
            *reinterpret_cast<float2*>(&C[(size_t)(r0 + mt * 16)     * ldc + c0 + nt * 8]) = v0;
            *reinterpret_cast<float2*>(&C[(size_t)(r0 + mt * 16 + 8) * ldc + c0 + nt * 8]) = v1;
        }
}

// ---------------------------------------------------------------------------
// RoPE (unchanged)
// ---------------------------------------------------------------------------
__global__ __launch_bounds__(256) void rope_kernel(float* __restrict__ qkv)
{
    int idx = blockIdx.x * 256 + threadIdx.x;
    int i = idx & 63;
    int h = (idx >> 6) & (NHEADS - 1);
    int t = (idx >> 10) & (SEQ - 1);
    int b = idx >> 21;

    double freq = exp(-9.210340371976184 * (double)(2 * i) / 128.0);
    double ang  = (double)t * freq;
    double sd, cd;
    sincos(ang, &sd, &cd);
    float s = (float)sd, c = (float)cd;

    size_t base = ((size_t)(b * SEQ + t)) * QKVDIM + h * DHEAD + 2 * i;
    float2 q = *reinterpret_cast<float2*>(&qkv[base]);
    float2 k = *reinterpret_cast<float2*>(&qkv[base + DMODEL]);
    float2 qo, ko;
    qo.x = q.x * c - q.y * s;  qo.y = q.y * c + q.x * s;
    ko.x = k.x * c - k.y * s;  ko.y = k.y * c + k.x * s;
    *reinterpret_cast<float2*>(&qkv[base])          = qo;
    *reinterpret_cast<float2*>(&qkv[base + DMODEL]) = ko;
}

// ---------------------------------------------------------------------------
// Flash attention (fp32 SIMT, unchanged from round 1 — passes @ 1.8e-6)
// ---------------------------------------------------------------------------
#define TQ 64
#define TK 64

struct AttnSmem {
    float Qt[DHEAD][65];
    float Kt[DHEAD][65];
    float V [TK][132];
    float S [TQ][65];
    float m[TQ], l[TQ], f[TQ];
};

__global__ __launch_bounds__(256) void attn_kernel(
    const float* __restrict__ qkv, float* __restrict__ out)
{
    extern __shared__ char smem_raw[];
    AttnSmem& sm = *reinterpret_cast<AttnSmem*>(smem_raw);

    const int qt = gridDim.x - 1 - blockIdx.x;
    const int h  = blockIdx.y;
    const int b  = blockIdx.z;
    const int tid = threadIdx.x;
    const int q0 = qt * TQ;
    const float scale = 0.08838834764831845f;

    const float* qbase = qkv + (size_t)b * SEQ * QKVDIM + h * DHEAD;

    for (int i = tid; i < TQ * 32; i += 256) {
        int r  = i >> 5;
        int d4 = i & 31;
        float4 v = *reinterpret_cast<const float4*>(
            qbase + (size_t)(q0 + r) * QKVDIM + d4 * 4);
        sm.Qt[d4*4+0][r] = v.x * scale;
        sm.Qt[d4*4+1][r] = v.y * scale;
        sm.Qt[d4*4+2][r] = v.z * scale;
        sm.Qt[d4*4+3][r] = v.w * scale;
    }
    if (tid < TQ) { sm.m[tid] = -1e30f; sm.l[tid] = 0.f; }

    float O[32];
#pragma unroll
    for (int j = 0; j < 32; j++) O[j] = 0.f;

    const int r_own = tid >> 2;
    const int c4    = tid & 3;
    const int tx    = tid & 15;
    const int ty    = tid >> 4;

    for (int kt = 0; kt <= qt; ++kt) {
        const int k0 = kt * TK;
        __syncthreads();

        const float* kbase = qkv + ((size_t)(b * SEQ) + k0) * QKVDIM + DMODEL + h * DHEAD;
        const float* vbase = kbase + DMODEL;
        for (int i = tid; i < TK * 32; i += 256) {
            int r  = i >> 5;
            int d4 = i & 31;
            float4 kv = *reinterpret_cast<const float4*>(kbase + (size_t)r * QKVDIM + d4 * 4);
            sm.Kt[d4*4+0][r] = kv.x; sm.Kt[d4*4+1][r] = kv.y;
            sm.Kt[d4*4+2][r] = kv.z; sm.Kt[d4*4+3][r] = kv.w;
            float4 vv = *reinterpret_cast<const float4*>(vbase + (size_t)r * QKVDIM + d4 * 4);
            *reinterpret_cast<float4*>(&sm.V[r][d4 * 4]) = vv;
        }
        __syncthreads();

        float acc[4][4];
#pragma unroll
        for (int i = 0; i < 4; i++)
#pragma unroll
            for (int j = 0; j < 4; j++) acc[i][j] = 0.f;

#pragma unroll 16
        for (int kk = 0; kk < DHEAD; ++kk) {
            float a0 = sm.Qt[kk][ty*4+0], a1 = sm.Qt[kk][ty*4+1];
            float a2 = sm.Qt[kk][ty*4+2], a3 = sm.Qt[kk][ty*4+3];
            float b0 = sm.Kt[kk][tx*4+0], b1 = sm.Kt[kk][tx*4+1];
            float b2 = sm.Kt[kk][tx*4+2], b3 = sm.Kt[kk][tx*4+3];
            acc[0][0] += a0*b0; acc[0][1] += a0*b1; acc[0][2] += a0*b2; acc[0][3] += a0*b3;
            acc[1][0] += a1*b0; acc[1][1] += a1*b1; acc[1][2] += a1*b2; acc[1][3] += a1*b3;
            acc[2][0] += a2*b0; acc[2][1] += a2*b1; acc[2][2] += a2*b2; acc[2][3] += a2*b3;
            acc[3][0] += a3*b0; acc[3][1] += a3*b1; acc[3][2] += a3*b2; acc[3][3] += a3*b3;
        }
#pragma unroll
        for (int i = 0; i < 4; i++) {
            int r = ty * 4 + i;
#pragma unroll
            for (int j = 0; j < 4; j++) {
                int c = tx * 4 + j;
                float v = acc[i][j];
                if (k0 + c > q0 + r) v = -1e30f;
                sm.S[r][c] = v;
            }
        }
        __syncthreads();

        if (tid < TQ) {
            int r = tid;
            float mo = sm.m[r];
            float mx = mo;
#pragma unroll 8
            for (int c = 0; c < TK; c++) mx = fmaxf(mx, sm.S[r][c]);
            float fac = __expf(mo - mx);
            float sum = 0.f;
#pragma unroll 8
            for (int c = 0; c < TK; c++) {
                float p = __expf(sm.S[r][c] - mx);
                sm.S[r][c] = p;
                sum += p;
            }
            sm.m[r] = mx;
            sm.l[r] = sm.l[r] * fac + sum;
            sm.f[r] = fac;
        }
        __syncthreads();

        float fac = sm.f[r_own];
#pragma unroll
        for (int j = 0; j < 32; j++) O[j] *= fac;

#pragma unroll 4
        for (int k = 0; k < TK; k++) {
            float p = sm.S[r_own][k];
#pragma unroll
            for (int jj = 0; jj < 8; jj++) {
                float4 vv = *reinterpret_cast<const float4*>(&sm.V[k][jj * 16 + c4 * 4]);
                O[jj*4+0] += p * vv.x;
                O[jj*4+1] += p * vv.y;
                O[jj*4+2] += p * vv.z;
                O[jj*4+3] += p * vv.w;
            }
        }
    }

    float invl = 1.f / sm.l[r_own];
    float* obase = out + ((size_t)(b * SEQ) + q0 + r_own) * DMODEL + h * DHEAD;
#pragma unroll
    for (int jj = 0; jj < 8; jj++) {
        float4 v;
        v.x = O[jj*4+0] * invl; v.y = O[jj*4+1] * invl;
        v.z = O[jj*4+2] * invl; v.w = O[jj*4+3] * invl;
        *reinterpret_cast<float4*>(obase + jj * 16 + c4 * 4) = v;
    }
}

// ---------------------------------------------------------------------------
extern "C" void kernel_launch(void* const* d_in, const int* in_sizes, int n_in,
                              void* d_out, int out_size)
{
    const float* x    = (const float*)d_in[0];
    const float* Wqkv = (const float*)d_in[1];
    const float* WO   = (const float*)d_in[2];
    float* out = (float*)d_out;

    float *qkv, *att;
    cudaGetSymbolAddress((void**)&qkv, g_qkv);
    cudaGetSymbolAddress((void**)&att, g_att);
    __nv_bfloat16 *xh, *xl, *wqh, *wql, *ah, *al, *wh, *wl;
    cudaGetSymbolAddress((void**)&xh, g_xh);   cudaGetSymbolAddress((void**)&xl, g_xl);
    cudaGetSymbolAddress((void**)&wqh, g_wqh); cudaGetSymbolAddress((void**)&wql, g_wql);
    cudaGetSymbolAddress((void**)&ah, g_ah);   cudaGetSymbolAddress((void**)&al, g_al);
    cudaGetSymbolAddress((void**)&wh, g_wh);   cudaGetSymbolAddress((void**)&wl, g_wl);

    cudaFuncSetAttribute(gemm_mma, cudaFuncAttributeMaxDynamicSharedMemorySize, GSMEM);

    // Split inputs to bf16 hi/lo
    { int n = MROWS * KDIM;   split_kernel<<<(n + 255) / 256, 256>>>(x, xh, xl, n); }
    { int n = QKVDIM * KDIM;  split_kernel<<<(n + 255) / 256, 256>>>(Wqkv, wqh, wql, n); }

    // 1) qkv = x @ Wqkv^T
    {
        dim3 grid(QKVDIM / BN, MROWS / BM);
        gemm_mma<<<grid, 256, GSMEM>>>(xh, xl, wqh, wql, qkv, QKVDIM);
    }

    // 2) RoPE in place
    {
        int total = BATCH * SEQ * NHEADS * (DHEAD / 2);
        rope_kernel<<<total / 256, 256>>>(qkv);
    }

    // 3) causal flash attention -> g_att
    {
        int smem = (int)sizeof(AttnSmem);
        cudaFuncSetAttribute(attn_kernel, cudaFuncAttributeMaxDynamicSharedMemorySize, smem);
        dim3 grid(SEQ / TQ, NHEADS, BATCH);
        attn_kernel<<<grid, 256, smem>>>(qkv, att);
    }

    // Split attention output and WO
    { int n = MROWS * KDIM;   split_kernel<<<(n + 255) / 256, 256>>>(att, ah, al, n); }
    { int n = DMODEL * KDIM;  split_kernel<<<(n + 255) / 256, 256>>>(WO, wh, wl, n); }

    // 4) out = att @ WO^T
    {
        dim3 grid(DMODEL / BN, MROWS / BM);
        gemm_mma<<<grid, 256, GSMEM>>>(ah, al, wh, wl, out, DMODEL);
    }
}

// round 4
// speedup vs baseline: 2.1772x; 1.5005x over previous
#include <cuda_runtime.h>
#include <cuda_bf16.h>
#include <cuda_fp16.h>
#include <math.h>
#include <stdint.h>

// Problem constants
#define BATCH   2
#define SEQ     2048
#define DMODEL  2048
#define NHEADS  16
#define DHEAD   128
#define MROWS   (BATCH*SEQ)          // 4096
#define QKVDIM  (3*DMODEL)           // 6144
#define KDIM    2048

// Scratch (__device__ globals; allocation-free rule)
__device__ float g_qkv[(size_t)MROWS * QKVDIM];
__device__ float2 g_rope[(size_t)SEQ * 64];
__device__ __nv_bfloat16 g_xh[(size_t)MROWS * KDIM],   g_xl[(size_t)MROWS * KDIM];
__device__ __nv_bfloat16 g_wqh[(size_t)QKVDIM * KDIM], g_wql[(size_t)QKVDIM * KDIM];
__device__ __nv_bfloat16 g_ah[(size_t)MROWS * KDIM],   g_al[(size_t)MROWS * KDIM];
__device__ __nv_bfloat16 g_wh[(size_t)DMODEL * KDIM],  g_wl[(size_t)DMODEL * KDIM];
// fp16 hi/lo attention operands, [B][H][T][D]
#define NATT ((size_t)BATCH * NHEADS * SEQ * DHEAD)
__device__ __half g_qh16[NATT], g_ql16[NATT];
__device__ __half g_kh16[NATT], g_kl16[NATT];
__device__ __half g_vh16[NATT], g_vl16[NATT];

// ---------------------------------------------------------------------------
// PTX helpers (sm_103-legal only; no tcgen05)
// ---------------------------------------------------------------------------
static __device__ __forceinline__ uint32_t smem_u32(const void* p) {
    uint32_t a;
    asm("{ .reg .u64 t; cvta.to.shared.u64 t, %1; cvt.u32.u64 %0, t; }" : "=r"(a) : "l"(p));
    return a;
}
static __device__ __forceinline__ void cpasync16(uint32_t dst, const void* src) {
    asm volatile("cp.async.cg.shared.global [%0], [%1], 16;\n" :: "r"(dst), "l"(src));
}
#define CP_COMMIT() asm volatile("cp.async.commit_group;\n" ::: "memory")
#define CP_WAIT0()  asm volatile("cp.async.wait_group 0;\n" ::: "memory")
#define CP_WAIT1()  asm volatile("cp.async.wait_group 1;\n" ::: "memory")

static __device__ __forceinline__ void ldsm_x4(uint32_t& r0, uint32_t& r1,
                                               uint32_t& r2, uint32_t& r3, uint32_t a) {
    asm volatile("ldmatrix.sync.aligned.m8n8.x4.shared.b16 {%0,%1,%2,%3}, [%4];"
                 : "=r"(r0), "=r"(r1), "=r"(r2), "=r"(r3) : "r"(a));
}
static __device__ __forceinline__ void ldsm_x2(uint32_t& r0, uint32_t& r1, uint32_t a) {
    asm volatile("ldmatrix.sync.aligned.m8n8.x2.shared.b16 {%0,%1}, [%2];"
                 : "=r"(r0), "=r"(r1) : "r"(a));
}
static __device__ __forceinline__ void ldsm_x4t(uint32_t& r0, uint32_t& r1,
                                                uint32_t& r2, uint32_t& r3, uint32_t a) {
    asm volatile("ldmatrix.sync.aligned.m8n8.x4.trans.shared.b16 {%0,%1,%2,%3}, [%4];"
                 : "=r"(r0), "=r"(r1), "=r"(r2), "=r"(r3) : "r"(a));
}
static __device__ __forceinline__ void mma_bf16(float* c, const uint32_t* a, const uint32_t* b) {
    asm volatile(
        "mma.sync.aligned.m16n8k16.row.col.f32.bf16.bf16.f32 "
        "{%0,%1,%2,%3}, {%4,%5,%6,%7}, {%8,%9}, {%0,%1,%2,%3};"
        : "+f"(c[0]), "+f"(c[1]), "+f"(c[2]), "+f"(c[3])
        : "r"(a[0]), "r"(a[1]), "r"(a[2]), "r"(a[3]), "r"(b[0]), "r"(b[1]));
}
static __device__ __forceinline__ void mma_f16(float* c, const uint32_t* a,
                                               uint32_t b0, uint32_t b1) {
    asm volatile(
        "mma.sync.aligned.m16n8k16.row.col.f32.f16.f16.f32 "
        "{%0,%1,%2,%3}, {%4,%5,%6,%7}, {%8,%9}, {%0,%1,%2,%3};"
        : "+f"(c[0]), "+f"(c[1]), "+f"(c[2]), "+f"(c[3])
        : "r"(a[0]), "r"(a[1]), "r"(a[2]), "r"(a[3]), "r"(b0), "r"(b1));
}
static __device__ __forceinline__ void pack_hl(float f0, float f1, uint32_t& hi, uint32_t& lo) {
    __half2 h = __floats2half2_rn(f0, f1);
    float2 fb = __half22float2(h);
    __half2 l2 = __floats2half2_rn(f0 - fb.x, f1 - fb.y);
    hi = *reinterpret_cast<uint32_t*>(&h);
    lo = *reinterpret_cast<uint32_t*>(&l2);
}

// ---------------------------------------------------------------------------
// fp32 -> bf16 hi/lo split (for GEMM operands)
// ---------------------------------------------------------------------------
__global__ __launch_bounds__(256) void split_kernel(
    const float* __restrict__ s, __nv_bfloat16* __restrict__ hi,
    __nv_bfloat16* __restrict__ lo, int n)
{
    int i = blockIdx.x * 256 + threadIdx.x;
    if (i >= n) return;
    float v = s[i];
    __nv_bfloat16 h = __float2bfloat16(v);
    hi[i] = h;
    lo[i] = __float2bfloat16(v - __bfloat162float(h));
}

// ---------------------------------------------------------------------------
// mma.sync GEMM (NT) — unchanged from round 3
// ---------------------------------------------------------------------------
#define BM 128
#define BN 128
#define BK 32
#define SROW 40
#define PART_BYTES (128 * SROW * 2)
#define STG_BYTES  (4 * PART_BYTES)
#define AH_OFF 0
#define AL_OFF PART_BYTES
#define BH_OFF (2 * PART_BYTES)
#define BL_OFF (3 * PART_BYTES)
#define GSMEM (2 * STG_BYTES)

static __device__ __forceinline__ void g_load_stage(
    uint32_t sb, int buf, int s, int bm, int bn, int tid,
    const __nv_bfloat16* __restrict__ Ah, const __nv_bfloat16* __restrict__ Al,
    const __nv_bfloat16* __restrict__ Bh, const __nv_bfloat16* __restrict__ Bl)
{
    uint32_t base = sb + buf * STG_BYTES;
    const int k0 = s * BK;
#pragma unroll
    for (int it = 0; it < 2; it++) {
        int idx = tid + it * 256;
        int r = idx >> 2, ch = idx & 3;
        uint32_t so = r * (SROW * 2) + ch * 16;
        size_t ga = (size_t)(bm + r) * KDIM + k0 + ch * 8;
        size_t gb = (size_t)(bn + r) * KDIM + k0 + ch * 8;
        cpasync16(base + AH_OFF + so, Ah + ga);
        cpasync16(base + AL_OFF + so, Al + ga);
        cpasync16(base + BH_OFF + so, Bh + gb);
        cpasync16(base + BL_OFF + so, Bl + gb);
    }
    CP_COMMIT();
}

__global__ __launch_bounds__(256, 2) void gemm_mma(
    const __nv_bfloat16* __restrict__ Ah, const __nv_bfloat16* __restrict__ Al,
    const __nv_bfloat16* __restrict__ Bh, const __nv_bfloat16* __restrict__ Bl,
    float* __restrict__ C, int ldc)
{
    extern __shared__ char smem[];
    uint32_t sb = smem_u32(smem);
    const int tid  = threadIdx.x;
    const int wid  = tid >> 5, lane = tid & 31;
    const int wm   = wid >> 2, wn = wid & 3;
    const int bm   = blockIdx.y * BM, bn = blockIdx.x * BN;

    float acc[4][4][4];
#pragma unroll
    for (int i = 0; i < 4; i++)
#pragma unroll
        for (int j = 0; j < 4; j++)
#pragma unroll
            for (int e = 0; e < 4; e++) acc[i][j][e] = 0.f;

    const uint32_t aRow = wm * 64 + (lane & 15);
    const uint32_t aCol = (lane >> 4) << 3;
    const uint32_t bRow = wn * 32 + (lane & 7);
    const uint32_t bCol = ((lane >> 3) & 1) << 3;

    g_load_stage(sb, 0, 0, bm, bn, tid, Ah, Al, Bh, Bl);

    const int NS = KDIM / BK;
    for (int s = 0; s < NS; s++) {
        const int buf = s & 1;
        if (s + 1 < NS) {
            g_load_stage(sb, buf ^ 1, s + 1, bm, bn, tid, Ah, Al, Bh, Bl);
            CP_WAIT1();
        } else {
            CP_WAIT0();
        }
        __syncthreads();

        uint32_t base = sb + buf * STG_BYTES;
#pragma unroll
        for (int kk = 0; kk < BK; kk += 16) {
            uint32_t af[4][4], bf[4][2];
#pragma unroll
            for (int mt = 0; mt < 4; mt++)
                ldsm_x4(af[mt][0], af[mt][1], af[mt][2], af[mt][3],
                        base + AH_OFF + (aRow + mt * 16) * (SROW * 2) + (aCol + kk) * 2);
#pragma unroll
            for (int nt = 0; nt < 4; nt++)
                ldsm_x2(bf[nt][0], bf[nt][1],
                        base + BH_OFF + (bRow + nt * 8) * (SROW * 2) + (bCol + kk) * 2);
#pragma unroll
            for (int mt = 0; mt < 4; mt++)
#pragma unroll
                for (int nt = 0; nt < 4; nt++) mma_bf16(acc[mt][nt], af[mt], bf[nt]);
#pragma unroll
            for (int mt = 0; mt < 4; mt++)
                ldsm_x4(af[mt][0], af[mt][1], af[mt][2], af[mt][3],
                        base + AL_OFF + (aRow + mt * 16) * (SROW * 2) + (aCol + kk) * 2);
#pragma unroll
            for (int mt = 0; mt < 4; mt++)
#pragma unroll
                for (int nt = 0; nt < 4; nt++) mma_bf16(acc[mt][nt], af[mt], bf[nt]);
#pragma unroll
            for (int nt = 0; nt < 4; nt++)
                ldsm_x2(bf[nt][0], bf[nt][1],
                        base + BL_OFF + (bRow + nt * 8) * (SROW * 2) + (bCol + kk) * 2);
#pragma unroll
            for (int mt = 0; mt < 4; mt++)
                ldsm_x4(af[mt][0], af[mt][1], af[mt][2], af[mt][3],
                        base + AH_OFF + (aRow + mt * 16) * (SROW * 2) + (aCol + kk) * 2);
#pragma unroll
            for (int mt = 0; mt < 4; mt++)
#pragma unroll
                for (int nt = 0; nt < 4; nt++) mma_bf16(acc[mt][nt], af[mt], bf[nt]);
        }
        __syncthreads();
    }

    const int r0 = bm + wm * 64 + (lane >> 2);
    const int c0 = bn + wn * 32 + 2 * (lane & 3);
#pragma unroll
    for (int mt = 0; mt < 4; mt++)
#pragma unroll
        for (int nt = 0; nt < 4; nt++) {
            float2 v0 = make_float2(acc[mt][nt][0], acc[mt][nt][1]);
            float2 v1 = make_float2(acc[mt][nt][2], acc[mt][nt][3]);
            *reinterpret_cast<float2*>(&C[(size_t)(r0 + mt * 16)     * ldc + c0 + nt * 8]) = v0;
            *reinterpret_cast<float2*>(&C[(size_t)(r0 + mt * 16 + 8) * ldc + c0 + nt * 8]) = v1;
        }
}

// ---------------------------------------------------------------------------
// RoPE cos/sin table (fp64, tiny)
// ---------------------------------------------------------------------------
__global__ __launch_bounds__(256) void rope_table_kernel(float2* __restrict__ tab)
{
    int idx = blockIdx.x * 256 + threadIdx.x;   // < 2048*64
    int i = idx & 63, t = idx >> 6;
    double freq = exp(-9.210340371976184 * (double)(2 * i) / 128.0);
    double sd, cd;
    sincos((double)t * freq, &sd, &cd);
    tab[idx] = make_float2((float)cd, (float)sd);
}

// ---------------------------------------------------------------------------
// Prep: qkv fp32 -> RoPE'd, scaled, fp16 hi/lo in [B][H][T][D] layout
// Q pre-scaled by (1/sqrt(128))*log2(e) so scores are in log2 units.
// ---------------------------------------------------------------------------
__global__ __launch_bounds__(256) void prep_kernel(
    const float* __restrict__ qkv, const float2* __restrict__ tab,
    __half* __restrict__ Qh, __half* __restrict__ Ql,
    __half* __restrict__ Kh, __half* __restrict__ Kl,
    __half* __restrict__ Vh, __half* __restrict__ Vl)
{
    int idx = blockIdx.x * 256 + threadIdx.x;   // < B*T*H*64
    int i = idx & 63;
    int h = (idx >> 6) & (NHEADS - 1);
    int t = (idx >> 10) & (SEQ - 1);
    int b = idx >> 21;
    const float QSCL = 0.1275174456f;           // log2(e)/sqrt(128)

    float2 cs = tab[t * 64 + i];
    size_t src = ((size_t)(b * SEQ + t)) * QKVDIM + h * DHEAD + 2 * i;
    float2 q = *reinterpret_cast<const float2*>(qkv + src);
    float2 k = *reinterpret_cast<const float2*>(qkv + src + DMODEL);
    float2 v = *reinterpret_cast<const float2*>(qkv + src + 2 * DMODEL);

    float qx = (q.x * cs.x - q.y * cs.y) * QSCL;
    float qy = (q.y * cs.x + q.x * cs.y) * QSCL;
    float kx = k.x * cs.x - k.y * cs.y;
    float ky = k.y * cs.x + k.x * cs.y;

    size_t dst = (((size_t)(b * NHEADS + h)) * SEQ + t) * DHEAD + 2 * i;
    uint32_t hi, lo;
    pack_hl(qx, qy, hi, lo);
    *reinterpret_cast<uint32_t*>(Qh + dst) = hi;
    *reinterpret_cast<uint32_t*>(Ql + dst) = lo;
    pack_hl(kx, ky, hi, lo);
    *reinterpret_cast<uint32_t*>(Kh + dst) = hi;
    *reinterpret_cast<uint32_t*>(Kl + dst) = lo;
    pack_hl(v.x, v.y, hi, lo);
    *reinterpret_cast<uint32_t*>(Vh + dst) = hi;
    *reinterpret_cast<uint32_t*>(Vl + dst) = lo;
}

// ---------------------------------------------------------------------------
// Flash attention via mma.sync fp16 hi/lo. TQ=128, TK=64, 8 warps.
// Writes output directly as bf16 hi/lo (WO GEMM operands).
// ---------------------------------------------------------------------------
#define AT_SROWB 272                   // 136 halves per padded row
#define SM_QH 0
#define SM_QL 34816
#define SM_K  69632                    // [buf][part], part=17408B, buf=34816B
#define SM_V  139264
#define AT_SMEM 208896
#define KPART 17408
#define KBUFS 34816

static __device__ __forceinline__ void at_load_kv(
    uint32_t sb, int buf, int kt, size_t bh, int tid,
    const __half* __restrict__ Kh, const __half* __restrict__ Kl,
    const __half* __restrict__ Vh, const __half* __restrict__ Vl)
{
    const int k0 = kt * 64;
#pragma unroll
    for (int it = 0; it < 16; it++) {
        int idx = tid + it * 256;            // 0..4095
        int part = idx >> 10;                // 0:Kh 1:Kl 2:Vh 3:Vl
        int rem = idx & 1023;
        int r = rem >> 4, ch = rem & 15;
        const __half* src = (part == 0) ? Kh : (part == 1) ? Kl : (part == 2) ? Vh : Vl;
        uint32_t dbase = (part < 2) ? (SM_K + buf * KBUFS + (part & 1) * KPART)
                                    : (SM_V + buf * KBUFS + (part & 1) * KPART);
        cpasync16(sb + dbase + r * AT_SROWB + ch * 16,
                  src + ((size_t)(bh + k0 + r)) * DHEAD + ch * 8);
    }
    CP_COMMIT();
}

__global__ __launch_bounds__(256, 1) void attn_mma(
    const __half* __restrict__ Qh, const __half* __restrict__ Ql,
    const __half* __restrict__ Kh, const __half* __restrict__ Kl,
    const __half* __restrict__ Vh, const __half* __restrict__ Vl,
    __nv_bfloat16* __restrict__ Oh, __nv_bfloat16* __restrict__ Ol)
{
    extern __shared__ char smem[];
    uint32_t sb = smem_u32(smem);
    const int tid = threadIdx.x, lane = tid & 31, w = tid >> 5;
    const int qt = gridDim.x - 1 - blockIdx.x;
    const int h = blockIdx.y, b = blockIdx.z;
    const int q0 = qt * 128;
    const size_t bh = (size_t)(b * NHEADS + h) * SEQ;   // row base in [BH][T]

    // Q load (2 parts x 2048 chunks of 16B)
    {
        const __half* gq0 = Qh + (bh + q0) * DHEAD;
        const __half* gq1 = Ql + (bh + q0) * DHEAD;
#pragma unroll
        for (int it = 0; it < 16; it++) {
            int idx = tid + it * 256;
            int part = idx >> 11, rem = idx & 2047;
            int r = rem >> 4, ch = rem & 15;
            const __half* src = part ? gq1 : gq0;
            cpasync16(sb + SM_QH + part * 34816 + r * AT_SROWB + ch * 16,
                      src + (size_t)r * DHEAD + ch * 8);
        }
        CP_COMMIT();
    }
    at_load_kv(sb, 0, 0, bh, tid, Kh, Kl, Vh, Vl);

    float m[2] = {-1e30f, -1e30f}, l[2] = {0.f, 0.f};
    float O[16][4];
#pragma unroll
    for (int i = 0; i < 16; i++)
#pragma unroll
        for (int e = 0; e < 4; e++) O[i][e] = 0.f;

    // ldmatrix lane addresses
    const uint32_t qha = sb + SM_QH + (w * 16 + (lane & 15)) * AT_SROWB + (((uint32_t)lane >> 4) << 3) * 2;
    const uint32_t qla = qha + 34816;
    const uint32_t koff = (lane & 7) * AT_SROWB + (((lane >> 3) & 1) << 3) * 2;
    const uint32_t voff = (lane & 15) * AT_SROWB + (((uint32_t)lane >> 4) << 3) * 2;

    const int nkt = 2 * qt + 2;
    for (int kt = 0; kt < nkt; kt++) {
        const int buf = kt & 1;
        __syncthreads();                       // prior reads of buf^1 done
        if (kt + 1 < nkt) {
            at_load_kv(sb, buf ^ 1, kt + 1, bh, tid, Kh, Kl, Vh, Vl);
            CP_WAIT1();
        } else {
            CP_WAIT0();
        }
        __syncthreads();

        // ---- S = Q K^T (3-term fp16 hi/lo), warp rows w*16..w*16+15 ----
        float sacc[8][4];
#pragma unroll
        for (int nt = 0; nt < 8; nt++)
#pragma unroll
            for (int e = 0; e < 4; e++) sacc[nt][e] = 0.f;

        const uint32_t kbase = sb + SM_K + buf * KBUFS;
#pragma unroll
        for (int ks = 0; ks < 8; ks++) {
            uint32_t qh[4], ql[4];
            ldsm_x4(qh[0], qh[1], qh[2], qh[3], qha + ks * 32);
            ldsm_x4(ql[0], ql[1], ql[2], ql[3], qla + ks * 32);
#pragma unroll
            for (int nt = 0; nt < 8; nt++) {
                uint32_t kh0, kh1, kl0, kl1;
                uint32_t ka = kbase + koff + nt * 8 * AT_SROWB + ks * 32;
                ldsm_x2(kh0, kh1, ka);
                ldsm_x2(kl0, kl1, ka + KPART);
                mma_f16(sacc[nt], qh, kh0, kh1);
                mma_f16(sacc[nt], ql, kh0, kh1);
                mma_f16(sacc[nt], qh, kl0, kl1);
            }
        }

        // ---- causal mask (diagonal tiles only) ----
        const int k0 = kt * 64;
        if (k0 + 63 > q0 + w * 16) {
            const int rA = q0 + w * 16 + (lane >> 2);
#pragma unroll
            for (int nt = 0; nt < 8; nt++) {
                int c = k0 + nt * 8 + 2 * (lane & 3);
                if (c     > rA)     sacc[nt][0] = -1e30f;
                if (c + 1 > rA)     sacc[nt][1] = -1e30f;
                if (c     > rA + 8) sacc[nt][2] = -1e30f;
                if (c + 1 > rA + 8) sacc[nt][3] = -1e30f;
            }
        }

        // ---- online softmax (scores already in log2 units) ----
        float mx0 = sacc[0][0], mx1 = sacc[0][2];
#pragma unroll
        for (int nt = 0; nt < 8; nt++) {
            mx0 = fmaxf(mx0, fmaxf(sacc[nt][0], sacc[nt][1]));
            mx1 = fmaxf(mx1, fmaxf(sacc[nt][2], sacc[nt][3]));
        }
        mx0 = fmaxf(mx0, __shfl_xor_sync(0xffffffffu, mx0, 1));
        mx0 = fmaxf(mx0, __shfl_xor_sync(0xffffffffu, mx0, 2));
        mx1 = fmaxf(mx1, __shfl_xor_sync(0xffffffffu, mx1, 1));
        mx1 = fmaxf(mx1, __shfl_xor_sync(0xffffffffu, mx1, 2));
        const float mn0 = fmaxf(m[0], mx0), mn1 = fmaxf(m[1], mx1);
        const float fac0 = exp2f(m[0] - mn0), fac1 = exp2f(m[1] - mn1);
        m[0] = mn0; m[1] = mn1;

        float s0 = 0.f, s1 = 0.f;
#pragma unroll
        for (int nt = 0; nt < 8; nt++) {
            sacc[nt][0] = exp2f(sacc[nt][0] - mn0);
            sacc[nt][1] = exp2f(sacc[nt][1] - mn0);
            sacc[nt][2] = exp2f(sacc[nt][2] - mn1);
            sacc[nt][3] = exp2f(sacc[nt][3] - mn1);
            s0 += sacc[nt][0] + sacc[nt][1];
            s1 += sacc[nt][2] + sacc[nt][3];
        }
        s0 += __shfl_xor_sync(0xffffffffu, s0, 1);
        s0 += __shfl_xor_sync(0xffffffffu, s0, 2);
        s1 += __shfl_xor_sync(0xffffffffu, s1, 1);
        s1 += __shfl_xor_sync(0xffffffffu, s1, 2);
        l[0] = l[0] * fac0 + s0;
        l[1] = l[1] * fac1 + s1;
#pragma unroll
        for (int i = 0; i < 16; i++) {
            O[i][0] *= fac0; O[i][1] *= fac0;
            O[i][2] *= fac1; O[i][3] *= fac1;
        }

        // ---- repack P into A-fragments (hi/lo fp16) ----
        uint32_t aPh[4][4], aPl[4][4];
#pragma unroll
        for (int ks = 0; ks < 4; ks++) {
            pack_hl(sacc[2*ks][0],   sacc[2*ks][1],   aPh[ks][0], aPl[ks][0]);
            pack_hl(sacc[2*ks][2],   sacc[2*ks][3],   aPh[ks][1], aPl[ks][1]);
            pack_hl(sacc[2*ks+1][0], sacc[2*ks+1][1], aPh[ks][2], aPl[ks][2]);
            pack_hl(sacc[2*ks+1][2], sacc[2*ks+1][3], aPh[ks][3], aPl[ks][3]);
        }

        // ---- O += P V (3-term) ----
        const uint32_t vbase = sb + SM_V + buf * KBUFS;
#pragma unroll
        for (int ks = 0; ks < 4; ks++) {
#pragma unroll
            for (int dt = 0; dt < 8; dt++) {
                uint32_t va = vbase + voff + ks * 16 * AT_SROWB + dt * 32;
                uint32_t vh0, vh1, vh2, vh3, vl0, vl1, vl2, vl3;
                ldsm_x4t(vh0, vh1, vh2, vh3, va);
                ldsm_x4t(vl0, vl1, vl2, vl3, va + KPART);
                mma_f16(O[2*dt],   aPh[ks], vh0, vh1);
                mma_f16(O[2*dt+1], aPh[ks], vh2, vh3);
                mma_f16(O[2*dt],   aPl[ks], vh0, vh1);
                mma_f16(O[2*dt+1], aPl[ks], vh2, vh3);
                mma_f16(O[2*dt],   aPh[ks], vl0, vl1);
                mma_f16(O[2*dt+1], aPh[ks], vl2, vl3);
            }
        }
    }

    // ---- normalize & write bf16 hi/lo to [b, t, h*128+d] ----
    const float inv0 = 1.f / l[0], inv1 = 1.f / l[1];
    const int rowA = q0 + w * 16 + (lane >> 2);
    const size_t baseA = ((size_t)b * SEQ + rowA) * DMODEL + h * DHEAD;
    const size_t baseB = baseA + (size_t)8 * DMODEL;
#pragma unroll
    for (int nt = 0; nt < 16; nt++) {
        int d = nt * 8 + 2 * (lane & 3);
        float o0 = O[nt][0] * inv0, o1 = O[nt][1] * inv0;
        float o2 = O[nt][2] * inv1, o3 = O[nt][3] * inv1;
        __nv_bfloat162 h0, l0h, h2, l2h;
        h0.x = __float2bfloat16(o0); h0.y = __float2bfloat16(o1);
        l0h.x = __float2bfloat16(o0 - __bfloat162float(h0.x));
        l0h.y = __float2bfloat16(o1 - __bfloat162float(h0.y));
        h2.x = __float2bfloat16(o2); h2.y = __float2bfloat16(o3);
        l2h.x = __float2bfloat16(o2 - __bfloat162float(h2.x));
        l2h.y = __float2bfloat16(o3 - __bfloat162float(h2.y));
        *reinterpret_cast<__nv_bfloat162*>(Oh + baseA + d) = h0;
        *reinterpret_cast<__nv_bfloat162*>(Ol + baseA + d) = l0h;
        *reinterpret_cast<__nv_bfloat162*>(Oh + baseB + d) = h2;
        *reinterpret_cast<__nv_bfloat162*>(Ol + baseB + d) = l2h;
    }
}

// ---------------------------------------------------------------------------
extern "C" void kernel_launch(void* const* d_in, const int* in_sizes, int n_in,
                              void* d_out, int out_size)
{
    const float* x    = (const float*)d_in[0];
    const float* Wqkv = (const float*)d_in[1];
    const float* WO   = (const float*)d_in[2];
    float* out = (float*)d_out;

    float *qkv;
    float2* rope;
    cudaGetSymbolAddress((void**)&qkv, g_qkv);
    cudaGetSymbolAddress((void**)&rope, g_rope);
    __nv_bfloat16 *xh, *xl, *wqh, *wql, *ah, *al, *wh, *wl;
    cudaGetSymbolAddress((void**)&xh, g_xh);   cudaGetSymbolAddress((void**)&xl, g_xl);
    cudaGetSymbolAddress((void**)&wqh, g_wqh); cudaGetSymbolAddress((void**)&wql, g_wql);
    cudaGetSymbolAddress((void**)&ah, g_ah);   cudaGetSymbolAddress((void**)&al, g_al);
    cudaGetSymbolAddress((void**)&wh, g_wh);   cudaGetSymbolAddress((void**)&wl, g_wl);
    __half *qh16, *ql16, *kh16, *kl16, *vh16, *vl16;
    cudaGetSymbolAddress((void**)&qh16, g_qh16); cudaGetSymbolAddress((void**)&ql16, g_ql16);
    cudaGetSymbolAddress((void**)&kh16, g_kh16); cudaGetSymbolAddress((void**)&kl16, g_kl16);
    cudaGetSymbolAddress((void**)&vh16, g_vh16); cudaGetSymbolAddress((void**)&vl16, g_vl16);

    cudaFuncSetAttribute(gemm_mma, cudaFuncAttributeMaxDynamicSharedMemorySize, GSMEM);
    cudaFuncSetAttribute(attn_mma, cudaFuncAttributeMaxDynamicSharedMemorySize, AT_SMEM);

    // Split inputs to bf16 hi/lo
    { int n = MROWS * KDIM;   split_kernel<<<(n + 255) / 256, 256>>>(x, xh, xl, n); }
    { int n = QKVDIM * KDIM;  split_kernel<<<(n + 255) / 256, 256>>>(Wqkv, wqh, wql, n); }

    // 1) qkv = x @ Wqkv^T
    {
        dim3 grid(QKVDIM / BN, MROWS / BM);
        gemm_mma<<<grid, 256, GSMEM>>>(xh, xl, wqh, wql, qkv, QKVDIM);
    }

    // 2) RoPE table + prep (rope, scale, fp16 hi/lo split, [B,H,T,D] layout)
    rope_table_kernel<<<(SEQ * 64) / 256, 256>>>(rope);
    {
        int total = BATCH * SEQ * NHEADS * 64;
        prep_kernel<<<total / 256, 256>>>(qkv, rope, qh16, ql16, kh16, kl16, vh16, vl16);
    }

    // 3) flash attention -> bf16 hi/lo (ah, al)
    {
        dim3 grid(SEQ / 128, NHEADS, BATCH);
        attn_mma<<<grid, 256, AT_SMEM>>>(qh16, ql16, kh16, kl16, vh16, vl16, ah, al);
    }

    // 4) out = att @ WO^T
    { int n = DMODEL * KDIM;  split_kernel<<<(n + 255) / 256, 256>>>(WO, wh, wl, n); }
    {
        dim3 grid(DMODEL / BN, MROWS / BM);
        gemm_mma<<<grid, 256, GSMEM>>>(ah, al, wh, wl, out, DMODEL);
    }
}

// round 5
// speedup vs baseline: 3.4226x; 1.5720x over previous
#include <cuda_runtime.h>
#include <cuda_bf16.h>
#include <cuda_fp16.h>
#include <math.h>
#include <stdint.h>

// Problem constants
#define BATCH   2
#define SEQ     2048
#define DMODEL  2048
#define NHEADS  16
#define DHEAD   128
#define MROWS   (BATCH*SEQ)          // 4096
#define QKVDIM  (3*DMODEL)           // 6144
#define KDIM    2048

// Scratch (__device__ globals; allocation-free rule)
__device__ float2 g_rope[(size_t)SEQ * 64];
__device__ __nv_bfloat16 g_xh[(size_t)MROWS * KDIM],   g_xl[(size_t)MROWS * KDIM];
__device__ __nv_bfloat16 g_wqh[(size_t)QKVDIM * KDIM], g_wql[(size_t)QKVDIM * KDIM];
__device__ __nv_bfloat16 g_ah[(size_t)MROWS * KDIM],   g_al[(size_t)MROWS * KDIM];
__device__ __nv_bfloat16 g_wh[(size_t)DMODEL * KDIM],  g_wl[(size_t)DMODEL * KDIM];
// fp16 hi/lo attention operands, [B][H][T][D]
#define NATT ((size_t)BATCH * NHEADS * SEQ * DHEAD)
__device__ __half g_qh16[NATT], g_ql16[NATT];
__device__ __half g_kh16[NATT], g_kl16[NATT];
__device__ __half g_vh16[NATT], g_vl16[NATT];

// ---------------------------------------------------------------------------
// PTX helpers (sm_103-legal only; no tcgen05)
// ---------------------------------------------------------------------------
static __device__ __forceinline__ uint32_t smem_u32(const void* p) {
    uint32_t a;
    asm("{ .reg .u64 t; cvta.to.shared.u64 t, %1; cvt.u32.u64 %0, t; }" : "=r"(a) : "l"(p));
    return a;
}
static __device__ __forceinline__ void cpasync16(uint32_t dst, const void* src) {
    asm volatile("cp.async.cg.shared.global [%0], [%1], 16;\n" :: "r"(dst), "l"(src));
}
#define CP_COMMIT() asm volatile("cp.async.commit_group;\n" ::: "memory")
#define CP_WAIT0()  asm volatile("cp.async.wait_group 0;\n" ::: "memory")
#define CP_WAIT1()  asm volatile("cp.async.wait_group 1;\n" ::: "memory")

static __device__ __forceinline__ void ldsm_x4(uint32_t& r0, uint32_t& r1,
                                               uint32_t& r2, uint32_t& r3, uint32_t a) {
    asm volatile("ldmatrix.sync.aligned.m8n8.x4.shared.b16 {%0,%1,%2,%3}, [%4];"
                 : "=r"(r0), "=r"(r1), "=r"(r2), "=r"(r3) : "r"(a));
}
static __device__ __forceinline__ void ldsm_x2(uint32_t& r0, uint32_t& r1, uint32_t a) {
    asm volatile("ldmatrix.sync.aligned.m8n8.x2.shared.b16 {%0,%1}, [%2];"
                 : "=r"(r0), "=r"(r1) : "r"(a));
}
static __device__ __forceinline__ void ldsm_x4t(uint32_t& r0, uint32_t& r1,
                                                uint32_t& r2, uint32_t& r3, uint32_t a) {
    asm volatile("ldmatrix.sync.aligned.m8n8.x4.trans.shared.b16 {%0,%1,%2,%3}, [%4];"
                 : "=r"(r0), "=r"(r1), "=r"(r2), "=r"(r3) : "r"(a));
}
static __device__ __forceinline__ void mma_bf16(float* c, const uint32_t* a, const uint32_t* b) {
    asm volatile(
        "mma.sync.aligned.m16n8k16.row.col.f32.bf16.bf16.f32 "
        "{%0,%1,%2,%3}, {%4,%5,%6,%7}, {%8,%9}, {%0,%1,%2,%3};"
        : "+f"(c[0]), "+f"(c[1]), "+f"(c[2]), "+f"(c[3])
        : "r"(a[0]), "r"(a[1]), "r"(a[2]), "r"(a[3]), "r"(b[0]), "r"(b[1]));
}
static __device__ __forceinline__ void mma_f16(float* c, const uint32_t* a,
                                               uint32_t b0, uint32_t b1) {
    asm volatile(
        "mma.sync.aligned.m16n8k16.row.col.f32.f16.f16.f32 "
        "{%0,%1,%2,%3}, {%4,%5,%6,%7}, {%8,%9}, {%0,%1,%2,%3};"
        : "+f"(c[0]), "+f"(c[1]), "+f"(c[2]), "+f"(c[3])
        : "r"(a[0]), "r"(a[1]), "r"(a[2]), "r"(a[3]), "r"(b0), "r"(b1));
}
static __device__ __forceinline__ void pack_hl(float f0, float f1, uint32_t& hi, uint32_t& lo) {
    __half2 h = __floats2half2_rn(f0, f1);
    float2 fb = __half22float2(h);
    __half2 l2 = __floats2half2_rn(f0 - fb.x, f1 - fb.y);
    hi = *reinterpret_cast<uint32_t*>(&h);
    lo = *reinterpret_cast<uint32_t*>(&l2);
}
// exp2 of two fp32 -> packed fp16x2 {lo=2^a, hi=2^b} via one MUFU op
static __device__ __forceinline__ uint32_t ex2_f16x2(float a, float b) {
    uint32_t d;
    asm("{ .reg .b32 t;\n cvt.rn.f16x2.f32 t, %2, %1;\n ex2.approx.f16x2 %0, t;\n}"
        : "=r"(d) : "f"(a), "f"(b));
    return d;
}

// ---------------------------------------------------------------------------
// fp32 -> bf16 hi/lo split (GEMM operands)
// ---------------------------------------------------------------------------
__global__ __launch_bounds__(256) void split_kernel(
    const float* __restrict__ s, __nv_bfloat16* __restrict__ hi,
    __nv_bfloat16* __restrict__ lo, int n)
{
    int i = blockIdx.x * 256 + threadIdx.x;
    if (i >= n) return;
    float v = s[i];
    __nv_bfloat16 h = __float2bfloat16(v);
    hi[i] = h;
    lo[i] = __float2bfloat16(v - __bfloat162float(h));
}

// ---------------------------------------------------------------------------
// RoPE cos/sin table (fp64, tiny)
// ---------------------------------------------------------------------------
__global__ __launch_bounds__(256) void rope_table_kernel(float2* __restrict__ tab)
{
    int idx = blockIdx.x * 256 + threadIdx.x;   // < 2048*64
    int i = idx & 63, t = idx >> 6;
    double freq = exp(-9.210340371976184 * (double)(2 * i) / 128.0);
    double sd, cd;
    sincos((double)t * freq, &sd, &cd);
    tab[idx] = make_float2((float)cd, (float)sd);
}

// ---------------------------------------------------------------------------
// Shared GEMM mainloop pieces (NT, bf16 hi/lo 3-term)
// BM=BN=128, BK=32, 256 threads, 8 warps (2m x 4n), warp tile 64x32.
// ---------------------------------------------------------------------------
#define BM 128
#define BN 128
#define BK 32
#define SROW 40
#define PART_BYTES (128 * SROW * 2)
#define STG_BYTES  (4 * PART_BYTES)
#define AH_OFF 0
#define AL_OFF PART_BYTES
#define BH_OFF (2 * PART_BYTES)
#define BL_OFF (3 * PART_BYTES)
#define GSMEM (2 * STG_BYTES)

static __device__ __forceinline__ void g_load_stage(
    uint32_t sb, int buf, int s, int bm, int bn, int tid,
    const __nv_bfloat16* __restrict__ Ah, const __nv_bfloat16* __restrict__ Al,
    const __nv_bfloat16* __restrict__ Bh, const __nv_bfloat16* __restrict__ Bl)
{
    uint32_t base = sb + buf * STG_BYTES;
    const int k0 = s * BK;
#pragma unroll
    for (int it = 0; it < 2; it++) {
        int idx = tid + it * 256;
        int r = idx >> 2, ch = idx & 3;
        uint32_t so = r * (SROW * 2) + ch * 16;
        size_t ga = (size_t)(bm + r) * KDIM + k0 + ch * 8;
        size_t gb = (size_t)(bn + r) * KDIM + k0 + ch * 8;
        cpasync16(base + AH_OFF + so, Ah + ga);
        cpasync16(base + AL_OFF + so, Al + ga);
        cpasync16(base + BH_OFF + so, Bh + gb);
        cpasync16(base + BL_OFF + so, Bl + gb);
    }
    CP_COMMIT();
}

// Mainloop: fills acc[4][4][4]; returns with smem free.
static __device__ __forceinline__ void g_mainloop(
    uint32_t sb, int bm, int bn, int tid, int lane, int wm, int wn,
    const __nv_bfloat16* __restrict__ Ah, const __nv_bfloat16* __restrict__ Al,
    const __nv_bfloat16* __restrict__ Bh, const __nv_bfloat16* __restrict__ Bl,
    float acc[4][4][4])
{
    const uint32_t aRow = wm * 64 + (lane & 15);
    const uint32_t aCol = (lane >> 4) << 3;
    const uint32_t bRow = wn * 32 + (lane & 7);
    const uint32_t bCol = ((lane >> 3) & 1) << 3;

    g_load_stage(sb, 0, 0, bm, bn, tid, Ah, Al, Bh, Bl);

    const int NS = KDIM / BK;
    for (int s = 0; s < NS; s++) {
        const int buf = s & 1;
        if (s + 1 < NS) {
            g_load_stage(sb, buf ^ 1, s + 1, bm, bn, tid, Ah, Al, Bh, Bl);
            CP_WAIT1();
        } else {
            CP_WAIT0();
        }
        __syncthreads();

        uint32_t base = sb + buf * STG_BYTES;
#pragma unroll
        for (int kk = 0; kk < BK; kk += 16) {
            uint32_t af[4][4], bf[4][2];
#pragma unroll
            for (int mt = 0; mt < 4; mt++)
                ldsm_x4(af[mt][0], af[mt][1], af[mt][2], af[mt][3],
                        base + AH_OFF + (aRow + mt * 16) * (SROW * 2) + (aCol + kk) * 2);
#pragma unroll
            for (int nt = 0; nt < 4; nt++)
                ldsm_x2(bf[nt][0], bf[nt][1],
                        base + BH_OFF + (bRow + nt * 8) * (SROW * 2) + (bCol + kk) * 2);
#pragma unroll
            for (int mt = 0; mt < 4; mt++)
#pragma unroll
                for (int nt = 0; nt < 4; nt++) mma_bf16(acc[mt][nt], af[mt], bf[nt]);
#pragma unroll
            for (int mt = 0; mt < 4; mt++)
                ldsm_x4(af[mt][0], af[mt][1], af[mt][2], af[mt][3],
                        base + AL_OFF + (aRow + mt * 16) * (SROW * 2) + (aCol + kk) * 2);
#pragma unroll
            for (int mt = 0; mt < 4; mt++)
#pragma unroll
                for (int nt = 0; nt < 4; nt++) mma_bf16(acc[mt][nt], af[mt], bf[nt]);
#pragma unroll
            for (int nt = 0; nt < 4; nt++)
                ldsm_x2(bf[nt][0], bf[nt][1],
                        base + BL_OFF + (bRow + nt * 8) * (SROW * 2) + (bCol + kk) * 2);
#pragma unroll
            for (int mt = 0; mt < 4; mt++)
                ldsm_x4(af[mt][0], af[mt][1], af[mt][2], af[mt][3],
                        base + AH_OFF + (aRow + mt * 16) * (SROW * 2) + (aCol + kk) * 2);
#pragma unroll
            for (int mt = 0; mt < 4; mt++)
#pragma unroll
                for (int nt = 0; nt < 4; nt++) mma_bf16(acc[mt][nt], af[mt], bf[nt]);
        }
        __syncthreads();
    }
}

// Plain fp32-output GEMM (used for WO projection)
__global__ __launch_bounds__(256, 2) void gemm_mma(
    const __nv_bfloat16* __restrict__ Ah, const __nv_bfloat16* __restrict__ Al,
    const __nv_bfloat16* __restrict__ Bh, const __nv_bfloat16* __restrict__ Bl,
    float* __restrict__ C, int ldc)
{
    extern __shared__ char smem[];
    uint32_t sb = smem_u32(smem);
    const int tid = threadIdx.x, wid = tid >> 5, lane = tid & 31;
    const int wm = wid >> 2, wn = wid & 3;
    const int bm = blockIdx.y * BM, bn = blockIdx.x * BN;

    float acc[4][4][4];
#pragma unroll
    for (int i = 0; i < 4; i++)
#pragma unroll
        for (int j = 0; j < 4; j++)
#pragma unroll
            for (int e = 0; e < 4; e++) acc[i][j][e] = 0.f;

    g_mainloop(sb, bm, bn, tid, lane, wm, wn, Ah, Al, Bh, Bl, acc);

    const int r0 = bm + wm * 64 + (lane >> 2);
    const int c0 = bn + wn * 32 + 2 * (lane & 3);
#pragma unroll
    for (int mt = 0; mt < 4; mt++)
#pragma unroll
        for (int nt = 0; nt < 4; nt++) {
            float2 v0 = make_float2(acc[mt][nt][0], acc[mt][nt][1]);
            float2 v1 = make_float2(acc[mt][nt][2], acc[mt][nt][3]);
            *reinterpret_cast<float2*>(&C[(size_t)(r0 + mt * 16)     * ldc + c0 + nt * 8]) = v0;
            *reinterpret_cast<float2*>(&C[(size_t)(r0 + mt * 16 + 8) * ldc + c0 + nt * 8]) = v1;
        }
}

// QKV GEMM with fused RoPE + fp16 hi/lo pack + [B,H,T,D] transpose epilogue.
// Each CTA's 128-col tile lies entirely in one (matrix, head).
__global__ __launch_bounds__(256, 2) void gemm_qkv(
    const __nv_bfloat16* __restrict__ Ah, const __nv_bfloat16* __restrict__ Al,
    const __nv_bfloat16* __restrict__ Bh, const __nv_bfloat16* __restrict__ Bl,
    const float2* __restrict__ tab,
    __half* __restrict__ Qh, __half* __restrict__ Ql,
    __half* __restrict__ Kh, __half* __restrict__ Kl,
    __half* __restrict__ Vh, __half* __restrict__ Vl)
{
    extern __shared__ char smem[];
    uint32_t sb = smem_u32(smem);
    const int tid = threadIdx.x, wid = tid >> 5, lane = tid & 31;
    const int wm = wid >> 2, wn = wid & 3;
    const int bm = blockIdx.y * BM, bn = blockIdx.x * BN;

    float acc[4][4][4];
#pragma unroll
    for (int i = 0; i < 4; i++)
#pragma unroll
        for (int j = 0; j < 4; j++)
#pragma unroll
            for (int e = 0; e < 4; e++) acc[i][j][e] = 0.f;

    g_mainloop(sb, bm, bn, tid, lane, wm, wn, Ah, Al, Bh, Bl, acc);

    // CTA-constant: which matrix (0=Q,1=K,2=V) and which head
    const int mat  = bn >> 11;
    const int head = (bn >> 7) & (NHEADS - 1);
    __half* Dh = (mat == 0) ? Qh : (mat == 1) ? Kh : Vh;
    __half* Dl = (mat == 0) ? Ql : (mat == 1) ? Kl : Vl;
    const float QSCL = 0.1275174456f;           // log2(e)/sqrt(128)

    const int r0 = bm + wm * 64 + (lane >> 2);  // global token row (rows same b)
    const int c0 = (bn & 127) + wn * 32 + 2 * (lane & 3);  // d within head (even)
    const int b  = r0 >> 11;
    const size_t obase = ((size_t)(b * NHEADS + head)) * SEQ * DHEAD;

#pragma unroll
    for (int mt = 0; mt < 4; mt++) {
        const int tA = (r0 + mt * 16) & (SEQ - 1);
        const int tB = tA + 8;
#pragma unroll
        for (int nt = 0; nt < 4; nt++) {
            const int d = c0 + nt * 8;
            float x0 = acc[mt][nt][0], x1 = acc[mt][nt][1];   // row tA: (d, d+1)
            float y0 = acc[mt][nt][2], y1 = acc[mt][nt][3];   // row tB
            if (mat < 2) {
                float2 csA = tab[tA * 64 + (d >> 1)];
                float2 csB = tab[tB * 64 + (d >> 1)];
                float nx0 = x0 * csA.x - x1 * csA.y;
                float nx1 = x1 * csA.x + x0 * csA.y;
                float ny0 = y0 * csB.x - y1 * csB.y;
                float ny1 = y1 * csB.x + y0 * csB.y;
                x0 = nx0; x1 = nx1; y0 = ny0; y1 = ny1;
                if (mat == 0) { x0 *= QSCL; x1 *= QSCL; y0 *= QSCL; y1 *= QSCL; }
            }
            uint32_t hi, lo;
            size_t dA = obase + (size_t)tA * DHEAD + d;
            size_t dB = obase + (size_t)tB * DHEAD + d;
            pack_hl(x0, x1, hi, lo);
            *reinterpret_cast<uint32_t*>(Dh + dA) = hi;
            *reinterpret_cast<uint32_t*>(Dl + dA) = lo;
            pack_hl(y0, y1, hi, lo);
            *reinterpret_cast<uint32_t*>(Dh + dB) = hi;
            *reinterpret_cast<uint32_t*>(Dl + dB) = lo;
        }
    }
}

// ---------------------------------------------------------------------------
// Flash attention via mma.sync. TQ=128, TK=64, 8 warps.
// S = QK^T 3-term fp16 hi/lo; P via ex2.approx.f16x2 (fp16-only);
// PV 2-term (Ph*Vh + Ph*Vl); row sums l via all-ones mma.
// ---------------------------------------------------------------------------
#define AT_SROWB 272                   // 136 halves per padded row
#define SM_QH 0
#define SM_QL 34816
#define SM_K  69632                    // [buf][part], part=17408B, buf=34816B
#define SM_V  139264
#define AT_SMEM 208896
#define KPART 17408
#define KBUFS 34816

static __device__ __forceinline__ void at_load_kv(
    uint32_t sb, int buf, int kt, size_t bh, int tid,
    const __half* __restrict__ Kh, const __half* __restrict__ Kl,
    const __half* __restrict__ Vh, const __half* __restrict__ Vl)
{
    const int k0 = kt * 64;
#pragma unroll
    for (int it = 0; it < 16; it++) {
        int idx = tid + it * 256;            // 0..4095
        int part = idx >> 10;                // 0:Kh 1:Kl 2:Vh 3:Vl
        int rem = idx & 1023;
        int r = rem >> 4, ch = rem & 15;
        const __half* src = (part == 0) ? Kh : (part == 1) ? Kl : (part == 2) ? Vh : Vl;
        uint32_t dbase = (part < 2) ? (SM_K + buf * KBUFS + (part & 1) * KPART)
                                    : (SM_V + buf * KBUFS + (part & 1) * KPART);
        cpasync16(sb + dbase + r * AT_SROWB + ch * 16,
                  src + ((size_t)(bh + k0 + r)) * DHEAD + ch * 8);
    }
    CP_COMMIT();
}

__global__ __launch_bounds__(256, 1) void attn_mma(
    const __half* __restrict__ Qh, const __half* __restrict__ Ql,
    const __half* __restrict__ Kh, const __half* __restrict__ Kl,
    const __half* __restrict__ Vh, const __half* __restrict__ Vl,
    __nv_bfloat16* __restrict__ Oh, __nv_bfloat16* __restrict__ Ol)
{
    extern __shared__ char smem[];
    uint32_t sb = smem_u32(smem);
    const int tid = threadIdx.x, lane = tid & 31, w = tid >> 5;
    const int qt = gridDim.x - 1 - blockIdx.x;
    const int h = blockIdx.y, b = blockIdx.z;
    const int q0 = qt * 128;
    const size_t bh = (size_t)(b * NHEADS + h) * SEQ;

    // Q load
    {
        const __half* gq0 = Qh + (bh + q0) * DHEAD;
        const __half* gq1 = Ql + (bh + q0) * DHEAD;
#pragma unroll
        for (int it = 0; it < 16; it++) {
            int idx = tid + it * 256;
            int part = idx >> 11, rem = idx & 2047;
            int r = rem >> 4, ch = rem & 15;
            const __half* src = part ? gq1 : gq0;
            cpasync16(sb + SM_QH + part * 34816 + r * AT_SROWB + ch * 16,
                      src + (size_t)r * DHEAD + ch * 8);
        }
        CP_COMMIT();
    }
    at_load_kv(sb, 0, 0, bh, tid, Kh, Kl, Vh, Vl);

    float m[2] = {-1e30f, -1e30f}, l[2] = {0.f, 0.f};
    float O[16][4];
#pragma unroll
    for (int i = 0; i < 16; i++)
#pragma unroll
        for (int e = 0; e < 4; e++) O[i][e] = 0.f;

    const uint32_t qha = sb + SM_QH + (w * 16 + (lane & 15)) * AT_SROWB + (((uint32_t)lane >> 4) << 3) * 2;
    const uint32_t qla = qha + 34816;
    const uint32_t koff = (lane & 7) * AT_SROWB + (((lane >> 3) & 1) << 3) * 2;
    const uint32_t voff = (lane & 15) * AT_SROWB + (((uint32_t)lane >> 4) << 3) * 2;
    const uint32_t ONES = 0x3C003C00u;   // fp16 {1.0, 1.0}

    const int nkt = 2 * qt + 2;
    for (int kt = 0; kt < nkt; kt++) {
        const int buf = kt & 1;
        __syncthreads();
        if (kt + 1 < nkt) {
            at_load_kv(sb, buf ^ 1, kt + 1, bh, tid, Kh, Kl, Vh, Vl);
            CP_WAIT1();
        } else {
            CP_WAIT0();
        }
        __syncthreads();

        // ---- S = Q K^T (3-term) ----
        float sacc[8][4];
#pragma unroll
        for (int nt = 0; nt < 8; nt++)
#pragma unroll
            for (int e = 0; e < 4; e++) sacc[nt][e] = 0.f;

        const uint32_t kbase = sb + SM_K + buf * KBUFS;
#pragma unroll
        for (int ks = 0; ks < 8; ks++) {
            uint32_t qh[4], ql[4];
            ldsm_x4(qh[0], qh[1], qh[2], qh[3], qha + ks * 32);
            ldsm_x4(ql[0], ql[1], ql[2], ql[3], qla + ks * 32);
#pragma unroll
            for (int nt = 0; nt < 8; nt++) {
                uint32_t kh0, kh1, kl0, kl1;
                uint32_t ka = kbase + koff + nt * 8 * AT_SROWB + ks * 32;
                ldsm_x2(kh0, kh1, ka);
                ldsm_x2(kl0, kl1, ka + KPART);
                mma_f16(sacc[nt], qh, kh0, kh1);
                mma_f16(sacc[nt], ql, kh0, kh1);
                mma_f16(sacc[nt], qh, kl0, kl1);
            }
        }

        // ---- causal mask (diagonal tiles only) ----
        const int k0 = kt * 64;
        if (k0 + 63 > q0 + w * 16) {
            const int rA = q0 + w * 16 + (lane >> 2);
#pragma unroll
            for (int nt = 0; nt < 8; nt++) {
                int c = k0 + nt * 8 + 2 * (lane & 3);
                if (c     > rA)     sacc[nt][0] = -1e30f;
                if (c + 1 > rA)     sacc[nt][1] = -1e30f;
                if (c     > rA + 8) sacc[nt][2] = -1e30f;
                if (c + 1 > rA + 8) sacc[nt][3] = -1e30f;
            }
        }

        // ---- online softmax: max + rescale factors (log2 units) ----
        float mx0 = sacc[0][0], mx1 = sacc[0][2];
#pragma unroll
        for (int nt = 0; nt < 8; nt++) {
            mx0 = fmaxf(mx0, fmaxf(sacc[nt][0], sacc[nt][1]));
            mx1 = fmaxf(mx1, fmaxf(sacc[nt][2], sacc[nt][3]));
        }
        mx0 = fmaxf(mx0, __shfl_xor_sync(0xffffffffu, mx0, 1));
        mx0 = fmaxf(mx0, __shfl_xor_sync(0xffffffffu, mx0, 2));
        mx1 = fmaxf(mx1, __shfl_xor_sync(0xffffffffu, mx1, 1));
        mx1 = fmaxf(mx1, __shfl_xor_sync(0xffffffffu, mx1, 2));
        const float mn0 = fmaxf(m[0], mx0), mn1 = fmaxf(m[1], mx1);
        const float fac0 = exp2f(m[0] - mn0), fac1 = exp2f(m[1] - mn1);
        m[0] = mn0; m[1] = mn1;

        // ---- P = 2^(s - mn) directly as fp16 A-fragments ----
        uint32_t aPh[4][4];
#pragma unroll
        for (int ks = 0; ks < 4; ks++) {
            aPh[ks][0] = ex2_f16x2(sacc[2*ks][0]   - mn0, sacc[2*ks][1]   - mn0);
            aPh[ks][1] = ex2_f16x2(sacc[2*ks][2]   - mn1, sacc[2*ks][3]   - mn1);
            aPh[ks][2] = ex2_f16x2(sacc[2*ks+1][0] - mn0, sacc[2*ks+1][1] - mn0);
            aPh[ks][3] = ex2_f16x2(sacc[2*ks+1][2] - mn1, sacc[2*ks+1][3] - mn1);
        }

        // ---- rescale O, then O += P V (2-term) and row sums via ones-mma ----
#pragma unroll
        for (int i = 0; i < 16; i++) {
            O[i][0] *= fac0; O[i][1] *= fac0;
            O[i][2] *= fac1; O[i][3] *= fac1;
        }
        float Olsum[4] = {0.f, 0.f, 0.f, 0.f};
        const uint32_t vbase = sb + SM_V + buf * KBUFS;
#pragma unroll
        for (int ks = 0; ks < 4; ks++) {
            mma_f16(Olsum, aPh[ks], ONES, ONES);
#pragma unroll
            for (int dt = 0; dt < 8; dt++) {
                uint32_t va = vbase + voff + ks * 16 * AT_SROWB + dt * 32;
                uint32_t vh0, vh1, vh2, vh3, vl0, vl1, vl2, vl3;
                ldsm_x4t(vh0, vh1, vh2, vh3, va);
                ldsm_x4t(vl0, vl1, vl2, vl3, va + KPART);
                mma_f16(O[2*dt],   aPh[ks], vh0, vh1);
                mma_f16(O[2*dt+1], aPh[ks], vh2, vh3);
                mma_f16(O[2*dt],   aPh[ks], vl0, vl1);
                mma_f16(O[2*dt+1], aPh[ks], vl2, vl3);
            }
        }
        l[0] = l[0] * fac0 + Olsum[0];
        l[1] = l[1] * fac1 + Olsum[2];
    }

    // ---- normalize & write bf16 hi/lo to [b, t, h*128+d] ----
    const float inv0 = 1.f / l[0], inv1 = 1.f / l[1];
    const int rowA = q0 + w * 16 + (lane >> 2);
    const size_t baseA = ((size_t)b * SEQ + rowA) * DMODEL + h * DHEAD;
    const size_t baseB = baseA + (size_t)8 * DMODEL;
#pragma unroll
    for (int nt = 0; nt < 16; nt++) {
        int d = nt * 8 + 2 * (lane & 3);
        float o0 = O[nt][0] * inv0, o1 = O[nt][1] * inv0;
        float o2 = O[nt][2] * inv1, o3 = O[nt][3] * inv1;
        __nv_bfloat162 h0, l0h, h2, l2h;
        h0.x = __float2bfloat16(o0); h0.y = __float2bfloat16(o1);
        l0h.x = __float2bfloat16(o0 - __bfloat162float(h0.x));
        l0h.y = __float2bfloat16(o1 - __bfloat162float(h0.y));
        h2.x = __float2bfloat16(o2); h2.y = __float2bfloat16(o3);
        l2h.x = __float2bfloat16(o2 - __bfloat162float(h2.x));
        l2h.y = __float2bfloat16(o3 - __bfloat162float(h2.y));
        *reinterpret_cast<__nv_bfloat162*>(Oh + baseA + d) = h0;
        *reinterpret_cast<__nv_bfloat162*>(Ol + baseA + d) = l0h;
        *reinterpret_cast<__nv_bfloat162*>(Oh + baseB + d) = h2;
        *reinterpret_cast<__nv_bfloat162*>(Ol + baseB + d) = l2h;
    }
}

// ---------------------------------------------------------------------------
extern "C" void kernel_launch(void* const* d_in, const int* in_sizes, int n_in,
                              void* d_out, int out_size)
{
    const float* x    = (const float*)d_in[0];
    const float* Wqkv = (const float*)d_in[1];
    const float* WO   = (const float*)d_in[2];
    float* out = (float*)d_out;

    float2* rope;
    cudaGetSymbolAddress((void**)&rope, g_rope);
    __nv_bfloat16 *xh, *xl, *wqh, *wql, *ah, *al, *wh, *wl;
    cudaGetSymbolAddress((void**)&xh, g_xh);   cudaGetSymbolAddress((void**)&xl, g_xl);
    cudaGetSymbolAddress((void**)&wqh, g_wqh); cudaGetSymbolAddress((void**)&wql, g_wql);
    cudaGetSymbolAddress((void**)&ah, g_ah);   cudaGetSymbolAddress((void**)&al, g_al);
    cudaGetSymbolAddress((void**)&wh, g_wh);   cudaGetSymbolAddress((void**)&wl, g_wl);
    __half *qh16, *ql16, *kh16, *kl16, *vh16, *vl16;
    cudaGetSymbolAddress((void**)&qh16, g_qh16); cudaGetSymbolAddress((void**)&ql16, g_ql16);
    cudaGetSymbolAddress((void**)&kh16, g_kh16); cudaGetSymbolAddress((void**)&kl16, g_kl16);
    cudaGetSymbolAddress((void**)&vh16, g_vh16); cudaGetSymbolAddress((void**)&vl16, g_vl16);

    cudaFuncSetAttribute(gemm_mma, cudaFuncAttributeMaxDynamicSharedMemorySize, GSMEM);
    cudaFuncSetAttribute(gemm_qkv, cudaFuncAttributeMaxDynamicSharedMemorySize, GSMEM);
    cudaFuncSetAttribute(attn_mma, cudaFuncAttributeMaxDynamicSharedMemorySize, AT_SMEM);

    // RoPE table + bf16 hi/lo splits
    rope_table_kernel<<<(SEQ * 64) / 256, 256>>>(rope);
    { int n = MROWS * KDIM;   split_kernel<<<(n + 255) / 256, 256>>>(x, xh, xl, n); }
    { int n = QKVDIM * KDIM;  split_kernel<<<(n + 255) / 256, 256>>>(Wqkv, wqh, wql, n); }
    { int n = DMODEL * KDIM;  split_kernel<<<(n + 255) / 256, 256>>>(WO, wh, wl, n); }

    // 1) QKV GEMM with fused RoPE + fp16 hi/lo pack + [B,H,T,D] transpose
    {
        dim3 grid(QKVDIM / BN, MROWS / BM);
        gemm_qkv<<<grid, 256, GSMEM>>>(xh, xl, wqh, wql, rope,
                                       qh16, ql16, kh16, kl16, vh16, vl16);
    }

    // 2) flash attention -> bf16 hi/lo (ah, al)
    {
        dim3 grid(SEQ / 128, NHEADS, BATCH);
        attn_mma<<<grid, 256, AT_SMEM>>>(qh16, ql16, kh16, kl16, vh16, vl16, ah, al);
    }

    // 3) out = att @ WO^T
    {
        dim3 grid(DMODEL / BN, MROWS / BM);
        gemm_mma<<<grid, 256, GSMEM>>>(ah, al, wh, wl, out, DMODEL);
    }
}

// round 6
// speedup vs baseline: 3.6210x; 1.0580x over previous
#include <cuda_runtime.h>
#include <cuda_bf16.h>
#include <cuda_fp16.h>
#include <math.h>
#include <stdint.h>

// Problem constants
#define BATCH   2
#define SEQ     2048
#define DMODEL  2048
#define NHEADS  16
#define DHEAD   128
#define MROWS   (BATCH*SEQ)          // 4096
#define QKVDIM  (3*DMODEL)           // 6144
#define KDIM    2048

// Scratch (__device__ globals; allocation-free rule)
__device__ float2 g_rope[(size_t)SEQ * 64];
__device__ __nv_bfloat16 g_xh[(size_t)MROWS * KDIM],   g_xl[(size_t)MROWS * KDIM];
__device__ __nv_bfloat16 g_wqh[(size_t)QKVDIM * KDIM], g_wql[(size_t)QKVDIM * KDIM];
__device__ __nv_bfloat16 g_ah[(size_t)MROWS * KDIM],   g_al[(size_t)MROWS * KDIM];
__device__ __nv_bfloat16 g_wh[(size_t)DMODEL * KDIM],  g_wl[(size_t)DMODEL * KDIM];
// fp16 hi/lo attention operands, [B][H][T][D]
#define NATT ((size_t)BATCH * NHEADS * SEQ * DHEAD)
__device__ __half g_qh16[NATT], g_ql16[NATT];
__device__ __half g_kh16[NATT];
__device__ __half g_vh16[NATT], g_vl16[NATT];

// ---------------------------------------------------------------------------
// PTX helpers (sm_103-legal only; no tcgen05)
// ---------------------------------------------------------------------------
static __device__ __forceinline__ uint32_t smem_u32(const void* p) {
    uint32_t a;
    asm("{ .reg .u64 t; cvta.to.shared.u64 t, %1; cvt.u32.u64 %0, t; }" : "=r"(a) : "l"(p));
    return a;
}
static __device__ __forceinline__ void cpasync16(uint32_t dst, const void* src) {
    asm volatile("cp.async.cg.shared.global [%0], [%1], 16;\n" :: "r"(dst), "l"(src));
}
#define CP_COMMIT() asm volatile("cp.async.commit_group;\n" ::: "memory")
#define CP_WAIT0()  asm volatile("cp.async.wait_group 0;\n" ::: "memory")
#define CP_WAIT1()  asm volatile("cp.async.wait_group 1;\n" ::: "memory")

static __device__ __forceinline__ void ldsm_x4(uint32_t& r0, uint32_t& r1,
                                               uint32_t& r2, uint32_t& r3, uint32_t a) {
    asm volatile("ldmatrix.sync.aligned.m8n8.x4.shared.b16 {%0,%1,%2,%3}, [%4];"
                 : "=r"(r0), "=r"(r1), "=r"(r2), "=r"(r3) : "r"(a));
}
static __device__ __forceinline__ void ldsm_x4t(uint32_t& r0, uint32_t& r1,
                                                uint32_t& r2, uint32_t& r3, uint32_t a) {
    asm volatile("ldmatrix.sync.aligned.m8n8.x4.trans.shared.b16 {%0,%1,%2,%3}, [%4];"
                 : "=r"(r0), "=r"(r1), "=r"(r2), "=r"(r3) : "r"(a));
}
static __device__ __forceinline__ void mma_bf16(float* c, const uint32_t* a,
                                                uint32_t b0, uint32_t b1) {
    asm volatile(
        "mma.sync.aligned.m16n8k16.row.col.f32.bf16.bf16.f32 "
        "{%0,%1,%2,%3}, {%4,%5,%6,%7}, {%8,%9}, {%0,%1,%2,%3};"
        : "+f"(c[0]), "+f"(c[1]), "+f"(c[2]), "+f"(c[3])
        : "r"(a[0]), "r"(a[1]), "r"(a[2]), "r"(a[3]), "r"(b0), "r"(b1));
}
static __device__ __forceinline__ void mma_f16(float* c, const uint32_t* a,
                                               uint32_t b0, uint32_t b1) {
    asm volatile(
        "mma.sync.aligned.m16n8k16.row.col.f32.f16.f16.f32 "
        "{%0,%1,%2,%3}, {%4,%5,%6,%7}, {%8,%9}, {%0,%1,%2,%3};"
        : "+f"(c[0]), "+f"(c[1]), "+f"(c[2]), "+f"(c[3])
        : "r"(a[0]), "r"(a[1]), "r"(a[2]), "r"(a[3]), "r"(b0), "r"(b1));
}
static __device__ __forceinline__ void pack_hl(float f0, float f1, uint32_t& hi, uint32_t& lo) {
    __half2 h = __floats2half2_rn(f0, f1);
    float2 fb = __half22float2(h);
    __half2 l2 = __floats2half2_rn(f0 - fb.x, f1 - fb.y);
    hi = *reinterpret_cast<uint32_t*>(&h);
    lo = *reinterpret_cast<uint32_t*>(&l2);
}
// exp2 of two fp32 -> packed fp16x2 {lo=2^a, hi=2^b} via one MUFU op
static __device__ __forceinline__ uint32_t ex2_f16x2(float a, float b) {
    uint32_t d;
    asm("{ .reg .b32 t;\n cvt.rn.f16x2.f32 t, %2, %1;\n ex2.approx.f16x2 %0, t;\n}"
        : "=r"(d) : "f"(a), "f"(b));
    return d;
}

// ---------------------------------------------------------------------------
// fp32 -> bf16 hi/lo split (GEMM operands)
// ---------------------------------------------------------------------------
__global__ __launch_bounds__(256) void split_kernel(
    const float* __restrict__ s, __nv_bfloat16* __restrict__ hi,
    __nv_bfloat16* __restrict__ lo, int n)
{
    int i = blockIdx.x * 256 + threadIdx.x;
    if (i >= n) return;
    float v = s[i];
    __nv_bfloat16 h = __float2bfloat16(v);
    hi[i] = h;
    lo[i] = __float2bfloat16(v - __bfloat162float(h));
}

// ---------------------------------------------------------------------------
// RoPE cos/sin table (fp64, tiny)
// ---------------------------------------------------------------------------
__global__ __launch_bounds__(256) void rope_table_kernel(float2* __restrict__ tab)
{
    int idx = blockIdx.x * 256 + threadIdx.x;   // < 2048*64
    int i = idx & 63, t = idx >> 6;
    double freq = exp(-9.210340371976184 * (double)(2 * i) / 128.0);
    double sd, cd;
    sincos((double)t * freq, &sd, &cd);
    tab[idx] = make_float2((float)cd, (float)sd);
}

// ---------------------------------------------------------------------------
// Shared GEMM mainloop (NT, bf16 hi/lo 3-term)
// BM=BN=128, BK=32, 256 threads, 8 warps (2m x 4n), warp tile 64x32.
// ---------------------------------------------------------------------------
#define BM 128
#define BN 128
#define BK 32
#define SROW 40
#define PART_BYTES (128 * SROW * 2)
#define STG_BYTES  (4 * PART_BYTES)
#define AH_OFF 0
#define AL_OFF PART_BYTES
#define BH_OFF (2 * PART_BYTES)
#define BL_OFF (3 * PART_BYTES)
#define GSMEM (2 * STG_BYTES)

static __device__ __forceinline__ void g_load_stage(
    uint32_t sb, int buf, int s, int bm, int bn, int tid,
    const __nv_bfloat16* __restrict__ Ah, const __nv_bfloat16* __restrict__ Al,
    const __nv_bfloat16* __restrict__ Bh, const __nv_bfloat16* __restrict__ Bl)
{
    uint32_t base = sb + buf * STG_BYTES;
    const int k0 = s * BK;
#pragma unroll
    for (int it = 0; it < 2; it++) {
        int idx = tid + it * 256;
        int r = idx >> 2, ch = idx & 3;
        uint32_t so = r * (SROW * 2) + ch * 16;
        size_t ga = (size_t)(bm + r) * KDIM + k0 + ch * 8;
        size_t gb = (size_t)(bn + r) * KDIM + k0 + ch * 8;
        cpasync16(base + AH_OFF + so, Ah + ga);
        cpasync16(base + AL_OFF + so, Al + ga);
        cpasync16(base + BH_OFF + so, Bh + gb);
        cpasync16(base + BL_OFF + so, Bl + gb);
    }
    CP_COMMIT();
}

// Mainloop: fills acc[4][4][4]; returns with smem free.
static __device__ __forceinline__ void g_mainloop(
    uint32_t sb, int bm, int bn, int tid, int lane, int wm, int wn,
    const __nv_bfloat16* __restrict__ Ah, const __nv_bfloat16* __restrict__ Al,
    const __nv_bfloat16* __restrict__ Bh, const __nv_bfloat16* __restrict__ Bl,
    float acc[4][4][4])
{
    const uint32_t aRow = wm * 64 + (lane & 15);
    const uint32_t aCol = (lane >> 4) << 3;
    // paired-x4 B fragments: 16 rows x 16 cols per ldsm_x4
    const uint32_t bOff = (wn * 32 + (lane & 7) + ((lane & 16) >> 1)) * (SROW * 2)
                        + (((lane >> 3) & 1) << 3) * 2;

    g_load_stage(sb, 0, 0, bm, bn, tid, Ah, Al, Bh, Bl);

    const int NS = KDIM / BK;
    for (int s = 0; s < NS; s++) {
        const int buf = s & 1;
        if (s + 1 < NS) {
            g_load_stage(sb, buf ^ 1, s + 1, bm, bn, tid, Ah, Al, Bh, Bl);
            CP_WAIT1();
        } else {
            CP_WAIT0();
        }
        __syncthreads();

        uint32_t base = sb + buf * STG_BYTES;
#pragma unroll
        for (int kk = 0; kk < BK; kk += 16) {
            uint32_t af[4][4], bh[4][2], bl[4][2];
            // load Ah + Bh + Bl fragments
#pragma unroll
            for (int mt = 0; mt < 4; mt++)
                ldsm_x4(af[mt][0], af[mt][1], af[mt][2], af[mt][3],
                        base + AH_OFF + (aRow + mt * 16) * (SROW * 2) + (aCol + kk) * 2);
#pragma unroll
            for (int np = 0; np < 2; np++) {
                ldsm_x4(bh[2*np][0], bh[2*np][1], bh[2*np+1][0], bh[2*np+1][1],
                        base + BH_OFF + bOff + np * 16 * (SROW * 2) + kk * 2);
                ldsm_x4(bl[2*np][0], bl[2*np][1], bl[2*np+1][0], bl[2*np+1][1],
                        base + BL_OFF + bOff + np * 16 * (SROW * 2) + kk * 2);
            }
            // Ah x Bh
#pragma unroll
            for (int mt = 0; mt < 4; mt++)
#pragma unroll
                for (int nt = 0; nt < 4; nt++)
                    mma_bf16(acc[mt][nt], af[mt], bh[nt][0], bh[nt][1]);
            // Ah x Bl
#pragma unroll
            for (int mt = 0; mt < 4; mt++)
#pragma unroll
                for (int nt = 0; nt < 4; nt++)
                    mma_bf16(acc[mt][nt], af[mt], bl[nt][0], bl[nt][1]);
            // Al x Bh (reload A only)
#pragma unroll
            for (int mt = 0; mt < 4; mt++)
                ldsm_x4(af[mt][0], af[mt][1], af[mt][2], af[mt][3],
                        base + AL_OFF + (aRow + mt * 16) * (SROW * 2) + (aCol + kk) * 2);
#pragma unroll
            for (int mt = 0; mt < 4; mt++)
#pragma unroll
                for (int nt = 0; nt < 4; nt++)
                    mma_bf16(acc[mt][nt], af[mt], bh[nt][0], bh[nt][1]);
        }
        __syncthreads();
    }
}

// Plain fp32-output GEMM (WO projection)
__global__ __launch_bounds__(256, 2) void gemm_mma(
    const __nv_bfloat16* __restrict__ Ah, const __nv_bfloat16* __restrict__ Al,
    const __nv_bfloat16* __restrict__ Bh, const __nv_bfloat16* __restrict__ Bl,
    float* __restrict__ C, int ldc)
{
    extern __shared__ char smem[];
    uint32_t sb = smem_u32(smem);
    const int tid = threadIdx.x, wid = tid >> 5, lane = tid & 31;
    const int wm = wid >> 2, wn = wid & 3;
    const int bm = blockIdx.y * BM, bn = blockIdx.x * BN;

    float acc[4][4][4];
#pragma unroll
    for (int i = 0; i < 4; i++)
#pragma unroll
        for (int j = 0; j < 4; j++)
#pragma unroll
            for (int e = 0; e < 4; e++) acc[i][j][e] = 0.f;

    g_mainloop(sb, bm, bn, tid, lane, wm, wn, Ah, Al, Bh, Bl, acc);

    const int r0 = bm + wm * 64 + (lane >> 2);
    const int c0 = bn + wn * 32 + 2 * (lane & 3);
#pragma unroll
    for (int mt = 0; mt < 4; mt++)
#pragma unroll
        for (int nt = 0; nt < 4; nt++) {
            float2 v0 = make_float2(acc[mt][nt][0], acc[mt][nt][1]);
            float2 v1 = make_float2(acc[mt][nt][2], acc[mt][nt][3]);
            *reinterpret_cast<float2*>(&C[(size_t)(r0 + mt * 16)     * ldc + c0 + nt * 8]) = v0;
            *reinterpret_cast<float2*>(&C[(size_t)(r0 + mt * 16 + 8) * ldc + c0 + nt * 8]) = v1;
        }
}

// QKV GEMM with fused RoPE + fp16 hi/lo pack + [B,H,T,D] transpose epilogue.
__global__ __launch_bounds__(256, 2) void gemm_qkv(
    const __nv_bfloat16* __restrict__ Ah, const __nv_bfloat16* __restrict__ Al,
    const __nv_bfloat16* __restrict__ Bh, const __nv_bfloat16* __restrict__ Bl,
    const float2* __restrict__ tab,
    __half* __restrict__ Qh, __half* __restrict__ Ql,
    __half* __restrict__ Kh,
    __half* __restrict__ Vh, __half* __restrict__ Vl)
{
    extern __shared__ char smem[];
    uint32_t sb = smem_u32(smem);
    const int tid = threadIdx.x, wid = tid >> 5, lane = tid & 31;
    const int wm = wid >> 2, wn = wid & 3;
    const int bm = blockIdx.y * BM, bn = blockIdx.x * BN;

    float acc[4][4][4];
#pragma unroll
    for (int i = 0; i < 4; i++)
#pragma unroll
        for (int j = 0; j < 4; j++)
#pragma unroll
            for (int e = 0; e < 4; e++) acc[i][j][e] = 0.f;

    g_mainloop(sb, bm, bn, tid, lane, wm, wn, Ah, Al, Bh, Bl, acc);

    const int mat  = bn >> 11;                  // 0=Q,1=K,2=V
    const int head = (bn >> 7) & (NHEADS - 1);
    const float QSCL = 0.1275174456f;           // log2(e)/sqrt(128)

    const int r0 = bm + wm * 64 + (lane >> 2);
    const int c0 = (bn & 127) + wn * 32 + 2 * (lane & 3);
    const int b  = r0 >> 11;
    const size_t obase = ((size_t)(b * NHEADS + head)) * SEQ * DHEAD;

#pragma unroll
    for (int mt = 0; mt < 4; mt++) {
        const int tA = (r0 + mt * 16) & (SEQ - 1);
        const int tB = tA + 8;
#pragma unroll
        for (int nt = 0; nt < 4; nt++) {
            const int d = c0 + nt * 8;
            float x0 = acc[mt][nt][0], x1 = acc[mt][nt][1];
            float y0 = acc[mt][nt][2], y1 = acc[mt][nt][3];
            if (mat < 2) {
                float2 csA = tab[tA * 64 + (d >> 1)];
                float2 csB = tab[tB * 64 + (d >> 1)];
                float nx0 = x0 * csA.x - x1 * csA.y;
                float nx1 = x1 * csA.x + x0 * csA.y;
                float ny0 = y0 * csB.x - y1 * csB.y;
                float ny1 = y1 * csB.x + y0 * csB.y;
                x0 = nx0; x1 = nx1; y0 = ny0; y1 = ny1;
                if (mat == 0) { x0 *= QSCL; x1 *= QSCL; y0 *= QSCL; y1 *= QSCL; }
            }
            size_t dA = obase + (size_t)tA * DHEAD + d;
            size_t dB = obase + (size_t)tB * DHEAD + d;
            uint32_t hi, lo;
            if (mat == 0) {
                pack_hl(x0, x1, hi, lo);
                *reinterpret_cast<uint32_t*>(Qh + dA) = hi;
                *reinterpret_cast<uint32_t*>(Ql + dA) = lo;
                pack_hl(y0, y1, hi, lo);
                *reinterpret_cast<uint32_t*>(Qh + dB) = hi;
                *reinterpret_cast<uint32_t*>(Ql + dB) = lo;
            } else if (mat == 1) {
                __half2 k0 = __floats2half2_rn(x0, x1);
                __half2 k1 = __floats2half2_rn(y0, y1);
                *reinterpret_cast<__half2*>(Kh + dA) = k0;
                *reinterpret_cast<__half2*>(Kh + dB) = k1;
            } else {
                pack_hl(x0, x1, hi, lo);
                *reinterpret_cast<uint32_t*>(Vh + dA) = hi;
                *reinterpret_cast<uint32_t*>(Vl + dA) = lo;
                pack_hl(y0, y1, hi, lo);
                *reinterpret_cast<uint32_t*>(Vh + dB) = hi;
                *reinterpret_cast<uint32_t*>(Vl + dB) = lo;
            }
        }
    }
}

// ---------------------------------------------------------------------------
// Flash attention via mma.sync. TQ=128, TK=64, 8 warps.
// S = QhKh + QlKh (2-term, no K-lo); P via ex2.approx.f16x2;
// PV 2-term (Ph*Vh + Ph*Vl); row sums via all-ones mma.
// ---------------------------------------------------------------------------
#define AT_SROWB 272                   // 136 halves per padded row
#define SM_QH 0
#define SM_QL 34816
#define SM_K  69632                    // [buf], 17408B each (Kh only)
#define SM_V  104448                   // [buf][part hi/lo]
#define AT_SMEM 174080
#define KPART 17408
#define VBUFS 34816

static __device__ __forceinline__ void at_load_kv(
    uint32_t sb, int buf, int kt, size_t bh, int tid,
    const __half* __restrict__ Kh,
    const __half* __restrict__ Vh, const __half* __restrict__ Vl)
{
    const int k0 = kt * 64;
#pragma unroll
    for (int it = 0; it < 12; it++) {
        int idx = tid + it * 256;            // 0..3071
        int part = idx >> 10;                // 0:Kh 1:Vh 2:Vl
        int rem = idx & 1023;
        int r = rem >> 4, ch = rem & 15;
        const __half* src = (part == 0) ? Kh : (part == 1) ? Vh : Vl;
        uint32_t dbase = (part == 0) ? (SM_K + buf * KPART)
                                     : (SM_V + buf * VBUFS + (part - 1) * KPART);
        cpasync16(sb + dbase + r * AT_SROWB + ch * 16,
                  src + ((size_t)(bh + k0 + r)) * DHEAD + ch * 8);
    }
    CP_COMMIT();
}

__global__ __launch_bounds__(256, 1) void attn_mma(
    const __half* __restrict__ Qh, const __half* __restrict__ Ql,
    const __half* __restrict__ Kh,
    const __half* __restrict__ Vh, const __half* __restrict__ Vl,
    __nv_bfloat16* __restrict__ Oh, __nv_bfloat16* __restrict__ Ol)
{
    extern __shared__ char smem[];
    uint32_t sb = smem_u32(smem);
    const int tid = threadIdx.x, lane = tid & 31, w = tid >> 5;
    const int qt = gridDim.x - 1 - blockIdx.x;
    const int h = blockIdx.y, b = blockIdx.z;
    const int q0 = qt * 128;
    const size_t bh = (size_t)(b * NHEADS + h) * SEQ;

    // Q load
    {
        const __half* gq0 = Qh + (bh + q0) * DHEAD;
        const __half* gq1 = Ql + (bh + q0) * DHEAD;
#pragma unroll
        for (int it = 0; it < 16; it++) {
            int idx = tid + it * 256;
            int part = idx >> 11, rem = idx & 2047;
            int r = rem >> 4, ch = rem & 15;
            const __half* src = part ? gq1 : gq0;
            cpasync16(sb + SM_QH + part * 34816 + r * AT_SROWB + ch * 16,
                      src + (size_t)r * DHEAD + ch * 8);
        }
        CP_COMMIT();
    }
    at_load_kv(sb, 0, 0, bh, tid, Kh, Vh, Vl);

    float m[2] = {-1e30f, -1e30f}, l[2] = {0.f, 0.f};
    float O[16][4];
#pragma unroll
    for (int i = 0; i < 16; i++)
#pragma unroll
        for (int e = 0; e < 4; e++) O[i][e] = 0.f;

    const uint32_t qha = sb + SM_QH + (w * 16 + (lane & 15)) * AT_SROWB + (((uint32_t)lane >> 4) << 3) * 2;
    const uint32_t qla = qha + 34816;
    // paired-x4 K fragments: 16 rows per ldsm_x4
    const uint32_t koff = ((lane & 7) + ((lane & 16) >> 1)) * AT_SROWB + (((lane >> 3) & 1) << 3) * 2;
    const uint32_t voff = (lane & 15) * AT_SROWB + (((uint32_t)lane >> 4) << 3) * 2;
    const uint32_t ONES = 0x3C003C00u;   // fp16 {1.0, 1.0}

    const int nkt = 2 * qt + 2;
    for (int kt = 0; kt < nkt; kt++) {
        const int buf = kt & 1;
        __syncthreads();
        if (kt + 1 < nkt) {
            at_load_kv(sb, buf ^ 1, kt + 1, bh, tid, Kh, Vh, Vl);
            CP_WAIT1();
        } else {
            CP_WAIT0();
        }
        __syncthreads();

        // ---- S = Q K^T (2-term: Qh*Kh + Ql*Kh) ----
        float sacc[8][4];
#pragma unroll
        for (int nt = 0; nt < 8; nt++)
#pragma unroll
            for (int e = 0; e < 4; e++) sacc[nt][e] = 0.f;

        const uint32_t kbase = sb + SM_K + buf * KPART;
#pragma unroll
        for (int ks = 0; ks < 8; ks++) {
            uint32_t qh[4], ql[4];
            ldsm_x4(qh[0], qh[1], qh[2], qh[3], qha + ks * 32);
            ldsm_x4(ql[0], ql[1], ql[2], ql[3], qla + ks * 32);
#pragma unroll
            for (int np = 0; np < 4; np++) {
                uint32_t k0r, k1r, k2r, k3r;
                ldsm_x4(k0r, k1r, k2r, k3r,
                        kbase + koff + np * 16 * AT_SROWB + ks * 32);
                mma_f16(sacc[2*np],   qh, k0r, k1r);
                mma_f16(sacc[2*np],   ql, k0r, k1r);
                mma_f16(sacc[2*np+1], qh, k2r, k3r);
                mma_f16(sacc[2*np+1], ql, k2r, k3r);
            }
        }

        // ---- causal mask (diagonal tiles only) ----
        const int k0 = kt * 64;
        if (k0 + 63 > q0 + w * 16) {
            const int rA = q0 + w * 16 + (lane >> 2);
#pragma unroll
            for (int nt = 0; nt < 8; nt++) {
                int c = k0 + nt * 8 + 2 * (lane & 3);
                if (c     > rA)     sacc[nt][0] = -1e30f;
                if (c + 1 > rA)     sacc[nt][1] = -1e30f;
                if (c     > rA + 8) sacc[nt][2] = -1e30f;
                if (c + 1 > rA + 8) sacc[nt][3] = -1e30f;
            }
        }

        // ---- online softmax (log2 units) ----
        float mx0 = sacc[0][0], mx1 = sacc[0][2];
#pragma unroll
        for (int nt = 0; nt < 8; nt++) {
            mx0 = fmaxf(mx0, fmaxf(sacc[nt][0], sacc[nt][1]));
            mx1 = fmaxf(mx1, fmaxf(sacc[nt][2], sacc[nt][3]));
        }
        mx0 = fmaxf(mx0, __shfl_xor_sync(0xffffffffu, mx0, 1));
        mx0 = fmaxf(mx0, __shfl_xor_sync(0xffffffffu, mx0, 2));
        mx1 = fmaxf(mx1, __shfl_xor_sync(0xffffffffu, mx1, 1));
        mx1 = fmaxf(mx1, __shfl_xor_sync(0xffffffffu, mx1, 2));
        const float mn0 = fmaxf(m[0], mx0), mn1 = fmaxf(m[1], mx1);
        const float fac0 = exp2f(m[0] - mn0), fac1 = exp2f(m[1] - mn1);
        m[0] = mn0; m[1] = mn1;

        // ---- P = 2^(s - mn) as fp16 A-fragments ----
        uint32_t aPh[4][4];
#pragma unroll
        for (int ks = 0; ks < 4; ks++) {
            aPh[ks][0] = ex2_f16x2(sacc[2*ks][0]   - mn0, sacc[2*ks][1]   - mn0);
            aPh[ks][1] = ex2_f16x2(sacc[2*ks][2]   - mn1, sacc[2*ks][3]   - mn1);
            aPh[ks][2] = ex2_f16x2(sacc[2*ks+1][0] - mn0, sacc[2*ks+1][1] - mn0);
            aPh[ks][3] = ex2_f16x2(sacc[2*ks+1][2] - mn1, sacc[2*ks+1][3] - mn1);
        }

        // ---- rescale O; O += P V (2-term); l via ones-mma ----
#pragma unroll
        for (int i = 0; i < 16; i++) {
            O[i][0] *= fac0; O[i][1] *= fac0;
            O[i][2] *= fac1; O[i][3] *= fac1;
        }
        float Olsum[4] = {0.f, 0.f, 0.f, 0.f};
        const uint32_t vbase = sb + SM_V + buf * VBUFS;
#pragma unroll
        for (int ks = 0; ks < 4; ks++) {
            mma_f16(Olsum, aPh[ks], ONES, ONES);
#pragma unroll
            for (int dt = 0; dt < 8; dt++) {
                uint32_t va = vbase + voff + ks * 16 * AT_SROWB + dt * 32;
                uint32_t vh0, vh1, vh2, vh3, vl0, vl1, vl2, vl3;
                ldsm_x4t(vh0, vh1, vh2, vh3, va);
                ldsm_x4t(vl0, vl1, vl2, vl3, va + KPART);
                mma_f16(O[2*dt],   aPh[ks], vh0, vh1);
                mma_f16(O[2*dt+1], aPh[ks], vh2, vh3);
                mma_f16(O[2*dt],   aPh[ks], vl0, vl1);
                mma_f16(O[2*dt+1], aPh[ks], vl2, vl3);
            }
        }
        l[0] = l[0] * fac0 + Olsum[0];
        l[1] = l[1] * fac1 + Olsum[2];
    }

    // ---- normalize & write bf16 hi/lo to [b, t, h*128+d] ----
    const float inv0 = 1.f / l[0], inv1 = 1.f / l[1];
    const int rowA = q0 + w * 16 + (lane >> 2);
    const size_t baseA = ((size_t)b * SEQ + rowA) * DMODEL + h * DHEAD;
    const size_t baseB = baseA + (size_t)8 * DMODEL;
#pragma unroll
    for (int nt = 0; nt < 16; nt++) {
        int d = nt * 8 + 2 * (lane & 3);
        float o0 = O[nt][0] * inv0, o1 = O[nt][1] * inv0;
        float o2 = O[nt][2] * inv1, o3 = O[nt][3] * inv1;
        __nv_bfloat162 h0, l0h, h2, l2h;
        h0.x = __float2bfloat16(o0); h0.y = __float2bfloat16(o1);
        l0h.x = __float2bfloat16(o0 - __bfloat162float(h0.x));
        l0h.y = __float2bfloat16(o1 - __bfloat162float(h0.y));
        h2.x = __float2bfloat16(o2); h2.y = __float2bfloat16(o3);
        l2h.x = __float2bfloat16(o2 - __bfloat162float(h2.x));
        l2h.y = __float2bfloat16(o3 - __bfloat162float(h2.y));
        *reinterpret_cast<__nv_bfloat162*>(Oh + baseA + d) = h0;
        *reinterpret_cast<__nv_bfloat162*>(Ol + baseA + d) = l0h;
        *reinterpret_cast<__nv_bfloat162*>(Oh + baseB + d) = h2;
        *reinterpret_cast<__nv_bfloat162*>(Ol + baseB + d) = l2h;
    }
}

// ---------------------------------------------------------------------------
extern "C" void kernel_launch(void* const* d_in, const int* in_sizes, int n_in,
                              void* d_out, int out_size)
{
    const float* x    = (const float*)d_in[0];
    const float* Wqkv = (const float*)d_in[1];
    const float* WO   = (const float*)d_in[2];
    float* out = (float*)d_out;

    float2* rope;
    cudaGetSymbolAddress((void**)&rope, g_rope);
    __nv_bfloat16 *xh, *xl, *wqh, *wql, *ah, *al, *wh, *wl;
    cudaGetSymbolAddress((void**)&xh, g_xh);   cudaGetSymbolAddress((void**)&xl, g_xl);
    cudaGetSymbolAddress((void**)&wqh, g_wqh); cudaGetSymbolAddress((void**)&wql, g_wql);
    cudaGetSymbolAddress((void**)&ah, g_ah);   cudaGetSymbolAddress((void**)&al, g_al);
    cudaGetSymbolAddress((void**)&wh, g_wh);   cudaGetSymbolAddress((void**)&wl, g_wl);
    __half *qh16, *ql16, *kh16, *vh16, *vl16;
    cudaGetSymbolAddress((void**)&qh16, g_qh16); cudaGetSymbolAddress((void**)&ql16, g_ql16);
    cudaGetSymbolAddress((void**)&kh16, g_kh16);
    cudaGetSymbolAddress((void**)&vh16, g_vh16); cudaGetSymbolAddress((void**)&vl16, g_vl16);

    cudaFuncSetAttribute(gemm_mma, cudaFuncAttributeMaxDynamicSharedMemorySize, GSMEM);
    cudaFuncSetAttribute(gemm_qkv, cudaFuncAttributeMaxDynamicSharedMemorySize, GSMEM);
    cudaFuncSetAttribute(attn_mma, cudaFuncAttributeMaxDynamicSharedMemorySize, AT_SMEM);

    // RoPE table + bf16 hi/lo splits
    rope_table_kernel<<<(SEQ * 64) / 256, 256>>>(rope);
    { int n = MROWS * KDIM;   split_kernel<<<(n + 255) / 256, 256>>>(x, xh, xl, n); }
    { int n = QKVDIM * KDIM;  split_kernel<<<(n + 255) / 256, 256>>>(Wqkv, wqh, wql, n); }
    { int n = DMODEL * KDIM;  split_kernel<<<(n + 255) / 256, 256>>>(WO, wh, wl, n); }

    // 1) QKV GEMM with fused RoPE + fp16 pack + [B,H,T,D] transpose
    {
        dim3 grid(QKVDIM / BN, MROWS / BM);
        gemm_qkv<<<grid, 256, GSMEM>>>(xh, xl, wqh, wql, rope,
                                       qh16, ql16, kh16, vh16, vl16);
    }

    // 2) flash attention -> bf16 hi/lo (ah, al)
    {
        dim3 grid(SEQ / 128, NHEADS, BATCH);
        attn_mma<<<grid, 256, AT_SMEM>>>(qh16, ql16, kh16, vh16, vl16, ah, al);
    }

    // 3) out = att @ WO^T
    {
        dim3 grid(DMODEL / BN, MROWS / BM);
        gemm_mma<<<grid, 256, GSMEM>>>(ah, al, wh, wl, out, DMODEL);
    }
}